// round 10
// baseline (speedup 1.0000x reference)
#include <cuda_runtime.h>
#include <cuda_fp16.h>
#include <cstdint>

// Problem constants
#define Bc 4
#define Sc 2048
#define Dc 1024
#define Hc 4096
#define Cc 32000
#define Mrows (Bc*Sc)   // 8192

// runtime flag bits
#define F_RELU    1
#define F_BIAS    2
#define F_CAUSAL  4
#define F_SWIZ    8
#define F_CAUSALK 16

// ======================= static scratch (no allocs) =======================
__device__ __half g_h_h[(size_t)Mrows*Dc],  g_h_l[(size_t)Mrows*Dc];
__device__ __half g_qwT_h[(size_t)Dc*Dc],   g_qwT_l[(size_t)Dc*Dc];
__device__ __half g_kwT_h[(size_t)Dc*Dc],   g_kwT_l[(size_t)Dc*Dc];
__device__ __half g_vwT_h[(size_t)Dc*Dc],   g_vwT_l[(size_t)Dc*Dc];
__device__ __half g_w1T_h[(size_t)Dc*Hc],   g_w1T_l[(size_t)Dc*Hc];
__device__ __half g_w2T_h[(size_t)Hc*Cc],   g_w2T_l[(size_t)Hc*Cc];
__device__ __half g_qx_h[(size_t)Mrows*Dc], g_qx_l[(size_t)Mrows*Dc];
__device__ __half g_kx_h[(size_t)Mrows*Dc], g_kx_l[(size_t)Mrows*Dc];
__device__ float  g_vx[(size_t)Mrows*Dc];
__device__ __half g_vxT_h[(size_t)Mrows*Dc],g_vxT_l[(size_t)Mrows*Dc]; // [b][Dc][Sc]
__device__ float  g_scores[(size_t)Bc*Sc*Sc];
__device__ __half g_p_h[(size_t)Bc*Sc*Sc],  g_p_l[(size_t)Bc*Sc*Sc];
__device__ float  g_a[(size_t)Mrows*Dc];
__device__ __half g_xn_h[(size_t)Mrows*Dc], g_xn_l[(size_t)Mrows*Dc];
__device__ __half g_hid_h[(size_t)Mrows*Hc],g_hid_l[(size_t)Mrows*Hc];

// ======================= helpers =======================
__device__ __forceinline__ uint32_t smem_u32(const void* p) {
    uint32_t a;
    asm("{ .reg .u64 t; cvta.to.shared.u64 t, %1; cvt.u32.u64 %0, t; }"
        : "=r"(a) : "l"(p));
    return a;
}
__device__ __forceinline__ void cp16(uint32_t dst, const void* src) {
    asm volatile("cp.async.cg.shared.global [%0], [%1], 16;"
                 :: "r"(dst), "l"(src) : "memory");
}
__device__ __forceinline__ void ldm4(uint32_t* r, uint32_t addr) {
    asm volatile("ldmatrix.sync.aligned.m8n8.x4.shared.b16 {%0,%1,%2,%3}, [%4];"
                 : "=r"(r[0]), "=r"(r[1]), "=r"(r[2]), "=r"(r[3]) : "r"(addr));
}
__device__ __forceinline__ void mma16816(float* c, const uint32_t* a, const uint32_t* b) {
    asm volatile(
        "mma.sync.aligned.m16n8k16.row.col.f32.f16.f16.f32 "
        "{%0,%1,%2,%3}, {%4,%5,%6,%7}, {%8,%9}, {%0,%1,%2,%3};"
        : "+f"(c[0]), "+f"(c[1]), "+f"(c[2]), "+f"(c[3])
        : "r"(a[0]), "r"(a[1]), "r"(a[2]), "r"(a[3]), "r"(b[0]), "r"(b[1]));
}
__device__ __forceinline__ void fsplit(float v, __half& h, __half& l) {
    h = __float2half(v);
    l = __float2half(v - __half2float(h));
}

// ======================= HMMA split-fp16 GEMM =======================
// C[M,N] = alpha*(A @ B^T) [+bias][relu].
// A: [M][Ks] fp16 hi/lo rows (first Kd used). B: [N][Ks] fp16 hi/lo rows.
// Kd = K extent (clamped by F_CAUSALK); Ks = row STRIDE (never clamped).
// TWOPROD=false: BN=128. Ah*Bh + Ah*Bl + Al*Bh (residual ~2^-22).
// TWOPROD=true:  BN=256. Ah*Bh + Al*Bh (B hi-only; residual A*Bl ~2^-12).
// CTA tile 128xBN, 8 warps (2m x 4n), BK=32, 3-stage cp.async.
// Smem row = 128B: [hi k0..31 | lo k0..31], chunk-xor swizzle.
// Output: fp32 (Cf != nullptr) or fp16 hi/lo split (Ch/Cl).
#define NSTAGE 3

template<bool TWOPROD>
__global__ void __launch_bounds__(256)
hmma_gemm(const __half* __restrict__ Ah, const __half* __restrict__ Al,
          const __half* __restrict__ Bh, const __half* __restrict__ Bl,
          const float* __restrict__ bias,
          float* __restrict__ Cf,
          __half* __restrict__ Ch, __half* __restrict__ Cl,
          int Nd, int Kd, int Ks, long sA, long sB, long sC,
          float alpha, int flags)
{
    constexpr int BN  = TWOPROD ? 256 : 128;   // CTA n-tile
    constexpr int NJ  = TWOPROD ? 8 : 4;       // n8 tiles per warp
    constexpr int WNW = TWOPROD ? 64 : 32;     // warp n width
    constexpr int SST = TWOPROD ? 49152 : 32768; // stage stride (A 16K + B 32K/16K)

    int m_tile, n_tile;
    if (flags & F_SWIZ) {             // L2-aware 1D swizzle, GROUP_M = 8
        const int numN = Nd / BN;
        const int pid = blockIdx.x;
        const int grp = 8 * numN;
        const int gid = pid / grp;
        m_tile = gid * 8 + (pid % 8);
        n_tile = (pid % grp) / 8;
    } else {
        m_tile = blockIdx.y;
        n_tile = blockIdx.x;
    }
    if ((flags & F_CAUSAL) && n_tile > m_tile) return;
    const int m0 = m_tile * 128, n0 = n_tile * BN;
    if (flags & F_CAUSALK) { const int kl = (m_tile + 1) * 128; if (kl < Kd) Kd = kl; }

    extern __shared__ char smem[];
    const uint32_t sbase = smem_u32(smem);

    const int tid = threadIdx.x, wid = tid >> 5, lid = tid & 31;
    const int wm = wid >> 2, wn = wid & 3;           // warp 2m x 4n
    const int mi = lid >> 3, r8 = lid & 7;           // ldmatrix lane roles

    Ah += blockIdx.z * sA;  Al += blockIdx.z * sA;
    Bh += blockIdx.z * sB;  Bl += blockIdx.z * sB;
    if (Cf) { Cf += blockIdx.z * sC; }
    else    { Ch += blockIdx.z * sC; Cl += blockIdx.z * sC; }

    // ---- stage loader. Addresses use Ks (stride); extent is Kd. ----
    auto stage_load = [&](int kc, int st) {
        const uint32_t sa = sbase + st * SST;
        const uint32_t sbB = sa + 16384;
        if (TWOPROD) {
            // A: 128 rows x 8 chunks (hi+lo)
#pragma unroll
            for (int jj = 0; jj < 4; jj++) {
                const int idx = tid + jj * 256;
                const int row = idx >> 3, c = idx & 7;
                const uint32_t sw = (uint32_t)((c ^ (row & 7)) << 4);
                const long ge = (long)kc * 32 + (c & 3) * 8;
                const __half* gA = (c < 4 ? Ah : Al) + (long)(m0 + row) * Ks + ge;
                cp16(sa + row * 128 + sw, gA);
            }
            // B: 256 rows x 4 chunks (hi only)
#pragma unroll
            for (int jj = 0; jj < 4; jj++) {
                const int idx = tid + jj * 256;
                const int row = idx >> 2, c = idx & 3;
                const uint32_t sw = (uint32_t)((c ^ (row & 7)) << 4);
                const long ge = (long)kc * 32 + c * 8;
                cp16(sbB + row * 128 + sw, Bh + (long)(n0 + row) * Ks + ge);
            }
        } else {
#pragma unroll
            for (int jj = 0; jj < 4; jj++) {
                const int idx = tid + jj * 256;
                const int row = idx >> 3, c = idx & 7;   // c: 0-3 hi, 4-7 lo
                const uint32_t sw = (uint32_t)((c ^ (row & 7)) << 4);
                const long ge = (long)kc * 32 + (c & 3) * 8;
                const __half* gA = (c < 4 ? Ah : Al) + (long)(m0 + row) * Ks + ge;
                cp16(sa + row * 128 + sw, gA);
                const __half* gB = (c < 4 ? Bh : Bl) + (long)(n0 + row) * Ks + ge;
                cp16(sbB + row * 128 + sw, gB);
            }
        }
        asm volatile("cp.async.commit_group;" ::: "memory");
    };

    float acc[4][NJ][4];
#pragma unroll
    for (int i = 0; i < 4; i++)
#pragma unroll
        for (int j = 0; j < NJ; j++)
#pragma unroll
            for (int r = 0; r < 4; r++) acc[i][j][r] = 0.f;

    const int ntiles = Kd >> 5;
    stage_load(0, 0);
    stage_load(1, 1);

    for (int t = 0; t < ntiles; t++) {
        if (t + 1 < ntiles) asm volatile("cp.async.wait_group 1;" ::: "memory");
        else                asm volatile("cp.async.wait_group 0;" ::: "memory");
        __syncthreads();
        if (t + 2 < ntiles) stage_load(t + 2, (t + 2) % NSTAGE);

        const uint32_t Ab = sbase + (t % NSTAGE) * SST;
        const uint32_t Bb = Ab + 16384;
#pragma unroll
        for (int ks = 0; ks < 2; ks++) {
            uint32_t a[2][4][4], b[2][NJ][2];
#pragma unroll
            for (int type = 0; type < 2; type++) {
                const int chunk = type * 4 + ks * 2 + (mi >> 1);
#pragma unroll
                for (int i = 0; i < 4; i++) {         // A: hi (type0) + lo (type1)
                    const int row = wm * 64 + i * 16 + (mi & 1) * 8 + r8;
                    ldm4(a[type][i], Ab + row * 128 + (((chunk ^ (row & 7))) << 4));
                }
                if (!TWOPROD || type == 0) {
#pragma unroll
                    for (int jj = 0; jj < NJ / 2; jj++) {  // B n8 tile pairs
                        const int row = wn * WNW + jj * 16 + (mi & 1) * 8 + r8;
                        uint32_t r4[4];
                        ldm4(r4, Bb + row * 128 + (((chunk ^ (row & 7))) << 4));
                        b[type][jj*2  ][0] = r4[0]; b[type][jj*2+1][0] = r4[1];
                        b[type][jj*2  ][1] = r4[2]; b[type][jj*2+1][1] = r4[3];
                    }
                }
            }
            // products
#pragma unroll
            for (int i = 0; i < 4; i++)
#pragma unroll
                for (int j = 0; j < NJ; j++) mma16816(acc[i][j], a[0][i], b[0][j]); // hi*hi
#pragma unroll
            for (int i = 0; i < 4; i++)
#pragma unroll
                for (int j = 0; j < NJ; j++) mma16816(acc[i][j], a[1][i], b[0][j]); // lo*hi
            if (!TWOPROD) {
#pragma unroll
                for (int i = 0; i < 4; i++)
#pragma unroll
                    for (int j = 0; j < NJ; j++) mma16816(acc[i][j], a[0][i], b[1][j]); // hi*lo
            }
        }
        __syncthreads();
    }

    // ---- epilogue: per thread, 2 rows x 2 cols per (i,j) fragment ----
    const int g = lid >> 2, tq = lid & 3;
    const bool do_bias = (flags & F_BIAS), do_relu = (flags & F_RELU);
#pragma unroll
    for (int i = 0; i < 4; i++) {
        const int row0 = m0 + wm * 64 + i * 16 + g;
#pragma unroll
        for (int j = 0; j < NJ; j++) {
            const int col = n0 + wn * WNW + j * 8 + tq * 2;
            float v0 = acc[i][j][0] * alpha, v1 = acc[i][j][1] * alpha;
            float v2 = acc[i][j][2] * alpha, v3 = acc[i][j][3] * alpha;
            if (do_bias) {
                const float b0 = bias[col], b1 = bias[col + 1];
                v0 += b0; v1 += b1; v2 += b0; v3 += b1;
            }
            if (do_relu) {
                v0 = fmaxf(v0, 0.f); v1 = fmaxf(v1, 0.f);
                v2 = fmaxf(v2, 0.f); v3 = fmaxf(v3, 0.f);
            }
            if (Cf) {
                *(float2*)(Cf + (long)row0 * Nd + col)       = make_float2(v0, v1);
                *(float2*)(Cf + (long)(row0 + 8) * Nd + col) = make_float2(v2, v3);
            } else {
                __half h0,l0,h1,l1,h2,l2,h3,l3;
                fsplit(v0,h0,l0); fsplit(v1,h1,l1); fsplit(v2,h2,l2); fsplit(v3,h3,l3);
                *(__half2*)(Ch + (long)row0 * Nd + col)       = __halves2half2(h0, h1);
                *(__half2*)(Cl + (long)row0 * Nd + col)       = __halves2half2(l0, l1);
                *(__half2*)(Ch + (long)(row0 + 8) * Nd + col) = __halves2half2(h2, h3);
                *(__half2*)(Cl + (long)(row0 + 8) * Nd + col) = __halves2half2(l2, l3);
            }
        }
    }
}

// ======================= aux kernels =======================
__global__ void embed_split(const int* __restrict__ x,
                            const float4* __restrict__ sem,
                            const float4* __restrict__ pos) {
    const int D4 = Dc / 4;
    int idx = blockIdx.x * 256 + threadIdx.x;
    int m = idx / D4, d4 = idx - m * D4;
    float4 a = sem[(size_t)x[m] * D4 + d4];
    float4 p = pos[(size_t)(m & (Sc - 1)) * D4 + d4];
    float v[4] = {a.x + p.x, a.y + p.y, a.z + p.z, a.w + p.w};
    __half h[4], l[4];
#pragma unroll
    for (int j = 0; j < 4; j++) fsplit(v[j], h[j], l[j]);
    __half2* oh = (__half2*)g_h_h + (size_t)idx * 2;
    __half2* ol = (__half2*)g_h_l + (size_t)idx * 2;
    oh[0] = __halves2half2(h[0], h[1]); oh[1] = __halves2half2(h[2], h[3]);
    ol[0] = __halves2half2(l[0], l[1]); ol[1] = __halves2half2(l[2], l[3]);
}

__global__ void transpose_split(const float* __restrict__ in,
                                __half* __restrict__ oh,
                                __half* __restrict__ ol,
                                int R, int Cn, long sIn, long sOut) {
    __shared__ float t[32][33];
    const long zb = blockIdx.z;
    const float* ip = in + zb * sIn;
    int c0 = blockIdx.x * 32, r0 = blockIdx.y * 32;
    int tx = threadIdx.x, ty = threadIdx.y;
#pragma unroll
    for (int j = 0; j < 4; j++)
        t[ty + 8*j][tx] = ip[(long)(r0 + ty + 8*j) * Cn + c0 + tx];
    __syncthreads();
#pragma unroll
    for (int j = 0; j < 4; j++) {
        float v = t[tx][ty + 8*j];
        __half h, l; fsplit(v, h, l);
        long o = zb * sOut + (long)(c0 + ty + 8*j) * R + r0 + tx;
        oh[o] = h; ol[o] = l;
    }
}

__global__ void softmax_split() {
    int row = blockIdx.x;
    int q = row & (Sc - 1);
    const float* sc = g_scores + (size_t)row * Sc;
    __half* ph_ = g_p_h + (size_t)row * Sc;
    __half* pl_ = g_p_l + (size_t)row * Sc;
    int len = q + 1, tid = threadIdx.x;
    __shared__ float red[8];

    float mx = -1e30f;
    for (int k = tid; k < len; k += 256) mx = fmaxf(mx, sc[k]);
#pragma unroll
    for (int o = 16; o; o >>= 1) mx = fmaxf(mx, __shfl_xor_sync(~0u, mx, o));
    if ((tid & 31) == 0) red[tid >> 5] = mx;
    __syncthreads();
    mx = red[0];
#pragma unroll
    for (int i = 1; i < 8; i++) mx = fmaxf(mx, red[i]);
    __syncthreads();

    float sum = 0.f;
    for (int k = tid; k < len; k += 256) sum += __expf(sc[k] - mx);
#pragma unroll
    for (int o = 16; o; o >>= 1) sum += __shfl_xor_sync(~0u, sum, o);
    if ((tid & 31) == 0) red[tid >> 5] = sum;
    __syncthreads();
    sum = 0.f;
#pragma unroll
    for (int i = 0; i < 8; i++) sum += red[i];
    float inv = 1.f / sum;

    for (int k = tid; k < Sc; k += 256) {
        float p = (k < len) ? __expf(sc[k] - mx) * inv : 0.f;
        __half h, l; fsplit(p, h, l);
        ph_[k] = h; pl_[k] = l;
    }
}

__global__ void layernorm_split(const float* __restrict__ gamma,
                                const float* __restrict__ beta) {
    int row = blockIdx.x, tid = threadIdx.x;
    float4 v = ((const float4*)(g_a + (size_t)row * Dc))[tid];
    __shared__ float red[8];

    float s = v.x + v.y + v.z + v.w;
#pragma unroll
    for (int o = 16; o; o >>= 1) s += __shfl_xor_sync(~0u, s, o);
    if ((tid & 31) == 0) red[tid >> 5] = s;
    __syncthreads();
    s = 0.f;
#pragma unroll
    for (int i = 0; i < 8; i++) s += red[i];
    float mu = s * (1.f / Dc);
    __syncthreads();

    float dx = v.x - mu, dy = v.y - mu, dz = v.z - mu, dw = v.w - mu;
    float qv = dx*dx + dy*dy + dz*dz + dw*dw;
#pragma unroll
    for (int o = 16; o; o >>= 1) qv += __shfl_xor_sync(~0u, qv, o);
    if ((tid & 31) == 0) red[tid >> 5] = qv;
    __syncthreads();
    qv = 0.f;
#pragma unroll
    for (int i = 0; i < 8; i++) qv += red[i];
    float inv = rsqrtf(qv * (1.f / Dc) + 1e-5f);

    float4 gg = ((const float4*)gamma)[tid];
    float4 bb = ((const float4*)beta)[tid];
    float o0 = dx*inv*gg.x + bb.x, o1 = dy*inv*gg.y + bb.y;
    float o2 = dz*inv*gg.z + bb.z, o3 = dw*inv*gg.w + bb.w;
    __half h[4], l[4];
    fsplit(o0, h[0], l[0]); fsplit(o1, h[1], l[1]);
    fsplit(o2, h[2], l[2]); fsplit(o3, h[3], l[3]);
    size_t o = (size_t)row * Dc / 2 + tid * 2;
    ((__half2*)g_xn_h)[o]   = __halves2half2(h[0], h[1]);
    ((__half2*)g_xn_h)[o+1] = __halves2half2(h[2], h[3]);
    ((__half2*)g_xn_l)[o]   = __halves2half2(l[0], l[1]);
    ((__half2*)g_xn_l)[o+1] = __halves2half2(l[2], l[3]);
}

// ======================= launch =======================
#define SYMADDR(p, s) cudaGetSymbolAddress((void**)&p, s)
#define SM3 (3*32768)
#define SM2 (3*49152)

extern "C" void kernel_launch(void* const* d_in, const int* in_sizes, int n_in,
                              void* d_out, int out_size) {
    const int*   x    = (const int*)  d_in[0];
    const float* sem  = (const float*)d_in[1];
    const float* pos  = (const float*)d_in[2];
    // d_in[3] = F — identity for attention_input='both'; skipped.
    const float* Qw   = (const float*)d_in[4];
    const float* Kw   = (const float*)d_in[5];
    const float* Vw   = (const float*)d_in[6];
    const float* ln_g = (const float*)d_in[7];
    const float* ln_b = (const float*)d_in[8];
    const float* W1   = (const float*)d_in[9];
    const float* b1   = (const float*)d_in[10];
    const float* W2   = (const float*)d_in[11];
    const float* b2   = (const float*)d_in[12];
    float* out = (float*)d_out;

    __half *hh,*hl,*qwh,*qwl,*kwh,*kwl,*vwh,*vwl,*w1h,*w1l,*w2h,*w2l;
    __half *qxh,*qxl,*kxh,*kxl,*vth,*vtl,*pph,*ppl,*xnh,*xnl,*hdh,*hdl;
    float *vx,*scp,*ap;
    SYMADDR(hh,  g_h_h);   SYMADDR(hl,  g_h_l);
    SYMADDR(qwh, g_qwT_h); SYMADDR(qwl, g_qwT_l);
    SYMADDR(kwh, g_kwT_h); SYMADDR(kwl, g_kwT_l);
    SYMADDR(vwh, g_vwT_h); SYMADDR(vwl, g_vwT_l);
    SYMADDR(w1h, g_w1T_h); SYMADDR(w1l, g_w1T_l);
    SYMADDR(w2h, g_w2T_h); SYMADDR(w2l, g_w2T_l);
    SYMADDR(qxh, g_qx_h);  SYMADDR(qxl, g_qx_l);
    SYMADDR(kxh, g_kx_h);  SYMADDR(kxl, g_kx_l);
    SYMADDR(vx,  g_vx);
    SYMADDR(vth, g_vxT_h); SYMADDR(vtl, g_vxT_l);
    SYMADDR(scp, g_scores);
    SYMADDR(pph, g_p_h);   SYMADDR(ppl, g_p_l);
    SYMADDR(ap,  g_a);
    SYMADDR(xnh, g_xn_h);  SYMADDR(xnl, g_xn_l);
    SYMADDR(hdh, g_hid_h); SYMADDR(hdl, g_hid_l);

    cudaFuncSetAttribute(hmma_gemm<false>, cudaFuncAttributeMaxDynamicSharedMemorySize, SM3);
    cudaFuncSetAttribute(hmma_gemm<true >, cudaFuncAttributeMaxDynamicSharedMemorySize, SM2);

    dim3 tb(32, 8);
    // weight transposes + split ([K][N] fp32 -> [N][K] fp16 hi/lo)
    transpose_split<<<dim3(Dc/32, Dc/32, 1), tb>>>(Qw, qwh, qwl, Dc, Dc, 0, 0);
    transpose_split<<<dim3(Dc/32, Dc/32, 1), tb>>>(Kw, kwh, kwl, Dc, Dc, 0, 0);
    transpose_split<<<dim3(Dc/32, Dc/32, 1), tb>>>(Vw, vwh, vwl, Dc, Dc, 0, 0);
    transpose_split<<<dim3(Hc/32, Dc/32, 1), tb>>>(W1, w1h, w1l, Dc, Hc, 0, 0);
    transpose_split<<<dim3(Cc/32, Hc/32, 1), tb>>>(W2, w2h, w2l, Hc, Cc, 0, 0);

    // embeddings (fp32 -> hi/lo)
    embed_split<<<(Mrows * (Dc/4)) / 256, 256>>>(x, (const float4*)sem,
                                                 (const float4*)pos);

    // QKV projections: 2-product (h split, weights hi-only), BN=256
    const int gQKV = (Mrows/128) * (Dc/256);
    hmma_gemm<true><<<gQKV, 256, SM2>>>(
        hh, hl, qwh, qwl, nullptr, nullptr, qxh, qxl,
        Dc, Dc, Dc, 0, 0, 0, 1.f, F_SWIZ);
    hmma_gemm<true><<<gQKV, 256, SM2>>>(
        hh, hl, kwh, kwl, nullptr, nullptr, kxh, kxl,
        Dc, Dc, Dc, 0, 0, 0, 1.f, F_SWIZ);
    hmma_gemm<true><<<gQKV, 256, SM2>>>(
        hh, hl, vwh, vwl, nullptr, vx, nullptr, nullptr,
        Dc, Dc, Dc, 0, 0, 0, 1.f, F_SWIZ);

    // Vx -> VxT hi/lo (per batch [Sc][Dc] -> [Dc][Sc])
    transpose_split<<<dim3(Dc/32, Sc/32, Bc), tb>>>(
        vx, vth, vtl, Sc, Dc, (long)Sc*Dc, (long)Dc*Sc);

    // scores = Qx @ Kx^T / 32, 3-product, causal tile-skip, batched
    hmma_gemm<false><<<dim3(Sc/128, Sc/128, Bc), 256, SM3>>>(
        qxh, qxl, kxh, kxl, nullptr, scp, nullptr, nullptr,
        Sc, Dc, Dc, (long)Sc*Dc, (long)Sc*Dc, (long)Sc*Sc, 0.03125f, F_CAUSAL);

    // softmax -> probs hi/lo
    softmax_split<<<Bc * Sc, 256>>>();

    // a = probs @ Vx, 3-product, causal K-limit (stride Sc preserved), batched
    hmma_gemm<false><<<dim3(Dc/128, Sc/128, Bc), 256, SM3>>>(
        pph, ppl, vth, vtl, nullptr, ap, nullptr, nullptr,
        Dc, Sc, Sc, (long)Sc*Sc, (long)Dc*Sc, (long)Sc*Dc, 1.f, F_CAUSALK);

    // LayerNorm -> xn hi/lo
    layernorm_split<<<Mrows, 256>>>(ln_g, ln_b);

    // hidden = relu(xn @ W1 + b1), 2-product, BN=256
    hmma_gemm<true><<<(Mrows/128)*(Hc/256), 256, SM2>>>(
        xnh, xnl, w1h, w1l, b1, nullptr, hdh, hdl,
        Hc, Dc, Dc, 0, 0, 0, 1.f, F_RELU | F_BIAS | F_SWIZ);

    // out = hidden @ W2 + b2, 2-product, BN=256 (dominant GEMM)
    hmma_gemm<true><<<(Mrows/128)*(Cc/256), 256, SM2>>>(
        hdh, hdl, w2h, w2l, b2, out, nullptr, nullptr,
        Cc, Hc, Hc, 0, 0, 0, 1.f, F_BIAS | F_SWIZ);
}

// round 13
// speedup vs baseline: 1.0483x; 1.0483x over previous
#include <cuda_runtime.h>
#include <cuda_fp16.h>
#include <cstdint>

// Problem constants
#define Bc 4
#define Sc 2048
#define Dc 1024
#define Hc 4096
#define Cc 32000
#define Mrows (Bc*Sc)   // 8192

// runtime flag bits
#define F_RELU    1
#define F_BIAS    2
#define F_CAUSAL  4
#define F_SWIZ    8
#define F_CAUSALK 16

// ======================= static scratch (no allocs) =======================
__device__ __half g_h_h[(size_t)Mrows*Dc],  g_h_l[(size_t)Mrows*Dc];
__device__ __half g_qwT_h[(size_t)Dc*Dc],   g_qwT_l[(size_t)Dc*Dc];
__device__ __half g_kwT_h[(size_t)Dc*Dc],   g_kwT_l[(size_t)Dc*Dc];
__device__ __half g_vwT_h[(size_t)Dc*Dc],   g_vwT_l[(size_t)Dc*Dc];
__device__ __half g_w1T_h[(size_t)Dc*Hc],   g_w1T_l[(size_t)Dc*Hc];
__device__ __half g_w2T_h[(size_t)Hc*Cc],   g_w2T_l[(size_t)Hc*Cc];
__device__ __half g_qx_h[(size_t)Mrows*Dc], g_qx_l[(size_t)Mrows*Dc];
__device__ __half g_kx_h[(size_t)Mrows*Dc], g_kx_l[(size_t)Mrows*Dc];
__device__ float  g_vx[(size_t)Mrows*Dc];
__device__ __half g_vxT_h[(size_t)Mrows*Dc],g_vxT_l[(size_t)Mrows*Dc]; // [b][Dc][Sc]
__device__ float  g_scores[(size_t)Bc*Sc*Sc];
__device__ __half g_p_h[(size_t)Bc*Sc*Sc],  g_p_l[(size_t)Bc*Sc*Sc];
__device__ float  g_a[(size_t)Mrows*Dc];
__device__ __half g_xn_h[(size_t)Mrows*Dc], g_xn_l[(size_t)Mrows*Dc];
__device__ __half g_hid_h[(size_t)Mrows*Hc],g_hid_l[(size_t)Mrows*Hc];

// ======================= helpers =======================
__device__ __forceinline__ uint32_t smem_u32(const void* p) {
    uint32_t a;
    asm("{ .reg .u64 t; cvta.to.shared.u64 t, %1; cvt.u32.u64 %0, t; }"
        : "=r"(a) : "l"(p));
    return a;
}
__device__ __forceinline__ void cp16(uint32_t dst, const void* src) {
    asm volatile("cp.async.cg.shared.global [%0], [%1], 16;"
                 :: "r"(dst), "l"(src) : "memory");
}
__device__ __forceinline__ void ldm4(uint32_t* r, uint32_t addr) {
    asm volatile("ldmatrix.sync.aligned.m8n8.x4.shared.b16 {%0,%1,%2,%3}, [%4];"
                 : "=r"(r[0]), "=r"(r[1]), "=r"(r[2]), "=r"(r[3]) : "r"(addr));
}
__device__ __forceinline__ void mma16816(float* c, const uint32_t* a, const uint32_t* b) {
    asm volatile(
        "mma.sync.aligned.m16n8k16.row.col.f32.f16.f16.f32 "
        "{%0,%1,%2,%3}, {%4,%5,%6,%7}, {%8,%9}, {%0,%1,%2,%3};"
        : "+f"(c[0]), "+f"(c[1]), "+f"(c[2]), "+f"(c[3])
        : "r"(a[0]), "r"(a[1]), "r"(a[2]), "r"(a[3]), "r"(b[0]), "r"(b[1]));
}
__device__ __forceinline__ void fsplit(float v, __half& h, __half& l) {
    h = __float2half(v);
    l = __float2half(v - __half2float(h));
}

// ======================= HMMA split-fp16 GEMM =======================
// C[M,N] = alpha*(A @ B^T) [+bias][relu].
// A: [M][Ks] fp16 hi/lo rows (first Kd used). B: [N][Ks] fp16 hi/lo rows.
// Kd = K extent (clamped by F_CAUSALK); Ks = row STRIDE (never clamped).
// TWOPROD=false: Ah*Bh + Ah*Bl + Al*Bh  (residual ~2^-22).
// TWOPROD=true:  Ah*Bh + Al*Bh          (B hi-only; residual A*Bl ~2^-12).
// CTA tile 128x128, 8 warps (2m x 4n, warp 64x32), BK=32, 3-stage cp.async.
// Smem row = 128B: [hi k0..31 | lo k0..31], chunk-xor swizzle.
// Output: fp32 (Cf != nullptr) or fp16 hi/lo split (Ch/Cl).
#define NSTAGE 3
#define SSTRIDE 32768           // 16KB A + 16KB B per stage
#define GSMEM_BYTES (NSTAGE*SSTRIDE)

template<bool TWOPROD>
__global__ void __launch_bounds__(256)
hmma_gemm(const __half* __restrict__ Ah, const __half* __restrict__ Al,
          const __half* __restrict__ Bh, const __half* __restrict__ Bl,
          const float* __restrict__ bias,
          float* __restrict__ Cf,
          __half* __restrict__ Ch, __half* __restrict__ Cl,
          int Nd, int Kd, int Ks, long sA, long sB, long sC,
          float alpha, int flags)
{
    int m_tile, n_tile;
    if (flags & F_SWIZ) {             // L2-aware 1D swizzle, GROUP_M = 8
        const int numN = Nd >> 7;
        const int pid = blockIdx.x;
        const int grp = 8 * numN;
        const int gid = pid / grp;
        m_tile = gid * 8 + (pid % 8);
        n_tile = (pid % grp) / 8;
    } else {
        m_tile = blockIdx.y;
        n_tile = blockIdx.x;
    }
    if ((flags & F_CAUSAL) && n_tile > m_tile) return;
    const int m0 = m_tile * 128, n0 = n_tile * 128;
    if (flags & F_CAUSALK) { const int kl = (m_tile + 1) * 128; if (kl < Kd) Kd = kl; }

    extern __shared__ char smem[];
    const uint32_t sbase = smem_u32(smem);

    const int tid = threadIdx.x, wid = tid >> 5, lid = tid & 31;
    const int wm = wid >> 2, wn = wid & 3;           // warp 2m x 4n
    const int mi = lid >> 3, r8 = lid & 7;           // ldmatrix lane roles

    Ah += blockIdx.z * sA;  Al += blockIdx.z * sA;
    Bh += blockIdx.z * sB;  Bl += blockIdx.z * sB;
    if (Cf) { Cf += blockIdx.z * sC; }
    else    { Ch += blockIdx.z * sC; Cl += blockIdx.z * sC; }

    // ---- stage loader (A always hi+lo; B lo skipped in TWOPROD) ----
    // Addresses use Ks (stride); loop extent uses Kd.
    auto stage_load = [&](int kc, int st) {
        const uint32_t sa = sbase + st * SSTRIDE;
        const uint32_t sbB = sa + 16384;
#pragma unroll
        for (int jj = 0; jj < 4; jj++) {
            const int idx = tid + jj * 256;
            const int row = idx >> 3, c = idx & 7;   // c: 0-3 hi, 4-7 lo
            const uint32_t sw = (uint32_t)((c ^ (row & 7)) << 4);
            const long ge = (long)kc * 32 + (c & 3) * 8;
            const __half* gA = (c < 4 ? Ah : Al) + (long)(m0 + row) * Ks + ge;
            cp16(sa + row * 128 + sw, gA);
            if (!TWOPROD || c < 4) {
                const __half* gB = (c < 4 ? Bh : Bl) + (long)(n0 + row) * Ks + ge;
                cp16(sbB + row * 128 + sw, gB);
            }
        }
        asm volatile("cp.async.commit_group;" ::: "memory");
    };

    float acc[4][4][4];
#pragma unroll
    for (int i = 0; i < 4; i++)
#pragma unroll
        for (int j = 0; j < 4; j++)
#pragma unroll
            for (int r = 0; r < 4; r++) acc[i][j][r] = 0.f;

    const int ntiles = Kd >> 5;
    stage_load(0, 0);
    stage_load(1, 1);

    for (int t = 0; t < ntiles; t++) {
        if (t + 1 < ntiles) asm volatile("cp.async.wait_group 1;" ::: "memory");
        else                asm volatile("cp.async.wait_group 0;" ::: "memory");
        __syncthreads();
        if (t + 2 < ntiles) stage_load(t + 2, (t + 2) % NSTAGE);

        const uint32_t Ab = sbase + (t % NSTAGE) * SSTRIDE;
        const uint32_t Bb = Ab + 16384;
#pragma unroll
        for (int ks = 0; ks < 2; ks++) {
            uint32_t a[2][4][4], b[2][4][2];
#pragma unroll
            for (int type = 0; type < 2; type++) {
                const int chunk = type * 4 + ks * 2 + (mi >> 1);
#pragma unroll
                for (int i = 0; i < 4; i++) {         // A: hi (type0) + lo (type1)
                    const int row = wm * 64 + i * 16 + (mi & 1) * 8 + r8;
                    ldm4(a[type][i], Ab + row * 128 + (((chunk ^ (row & 7))) << 4));
                }
                if (!TWOPROD || type == 0) {
#pragma unroll
                    for (int jj = 0; jj < 2; jj++) {  // B: 2 x (two n8 tiles)
                        const int row = wn * 32 + jj * 16 + (mi & 1) * 8 + r8;
                        uint32_t r4[4];
                        ldm4(r4, Bb + row * 128 + (((chunk ^ (row & 7))) << 4));
                        b[type][jj*2  ][0] = r4[0]; b[type][jj*2+1][0] = r4[1];
                        b[type][jj*2  ][1] = r4[2]; b[type][jj*2+1][1] = r4[3];
                    }
                }
            }
            // products
#pragma unroll
            for (int i = 0; i < 4; i++)
#pragma unroll
                for (int j = 0; j < 4; j++) mma16816(acc[i][j], a[0][i], b[0][j]);   // hi*hi
#pragma unroll
            for (int i = 0; i < 4; i++)
#pragma unroll
                for (int j = 0; j < 4; j++) mma16816(acc[i][j], a[1][i], b[0][j]);   // lo*hi
            if (!TWOPROD) {
#pragma unroll
                for (int i = 0; i < 4; i++)
#pragma unroll
                    for (int j = 0; j < 4; j++) mma16816(acc[i][j], a[0][i], b[1][j]); // hi*lo
            }
        }
        __syncthreads();
    }

    // ---- epilogue: per thread, 2 rows x 2 cols per (i,j) fragment ----
    const int g = lid >> 2, tq = lid & 3;
    const bool do_bias = (flags & F_BIAS), do_relu = (flags & F_RELU);
#pragma unroll
    for (int i = 0; i < 4; i++) {
        const int row0 = m0 + wm * 64 + i * 16 + g;
#pragma unroll
        for (int j = 0; j < 4; j++) {
            const int col = n0 + wn * 32 + j * 8 + tq * 2;
            float v0 = acc[i][j][0] * alpha, v1 = acc[i][j][1] * alpha;
            float v2 = acc[i][j][2] * alpha, v3 = acc[i][j][3] * alpha;
            if (do_bias) {
                const float b0 = bias[col], b1 = bias[col + 1];
                v0 += b0; v1 += b1; v2 += b0; v3 += b1;
            }
            if (do_relu) {
                v0 = fmaxf(v0, 0.f); v1 = fmaxf(v1, 0.f);
                v2 = fmaxf(v2, 0.f); v3 = fmaxf(v3, 0.f);
            }
            if (Cf) {
                *(float2*)(Cf + (long)row0 * Nd + col)       = make_float2(v0, v1);
                *(float2*)(Cf + (long)(row0 + 8) * Nd + col) = make_float2(v2, v3);
            } else {
                __half h0,l0,h1,l1,h2,l2,h3,l3;
                fsplit(v0,h0,l0); fsplit(v1,h1,l1); fsplit(v2,h2,l2); fsplit(v3,h3,l3);
                *(__half2*)(Ch + (long)row0 * Nd + col)       = __halves2half2(h0, h1);
                *(__half2*)(Cl + (long)row0 * Nd + col)       = __halves2half2(l0, l1);
                *(__half2*)(Ch + (long)(row0 + 8) * Nd + col) = __halves2half2(h2, h3);
                *(__half2*)(Cl + (long)(row0 + 8) * Nd + col) = __halves2half2(l2, l3);
            }
        }
    }
}

// ======================= aux kernels =======================
__global__ void embed_split(const int* __restrict__ x,
                            const float4* __restrict__ sem,
                            const float4* __restrict__ pos) {
    const int D4 = Dc / 4;
    int idx = blockIdx.x * 256 + threadIdx.x;
    int m = idx / D4, d4 = idx - m * D4;
    float4 a = sem[(size_t)x[m] * D4 + d4];
    float4 p = pos[(size_t)(m & (Sc - 1)) * D4 + d4];
    float v[4] = {a.x + p.x, a.y + p.y, a.z + p.z, a.w + p.w};
    __half h[4], l[4];
#pragma unroll
    for (int j = 0; j < 4; j++) fsplit(v[j], h[j], l[j]);
    __half2* oh = (__half2*)g_h_h + (size_t)idx * 2;
    __half2* ol = (__half2*)g_h_l + (size_t)idx * 2;
    oh[0] = __halves2half2(h[0], h[1]); oh[1] = __halves2half2(h[2], h[3]);
    ol[0] = __halves2half2(l[0], l[1]); ol[1] = __halves2half2(l[2], l[3]);
}

__global__ void transpose_split(const float* __restrict__ in,
                                __half* __restrict__ oh,
                                __half* __restrict__ ol,
                                int R, int Cn, long sIn, long sOut) {
    __shared__ float t[32][33];
    const long zb = blockIdx.z;
    const float* ip = in + zb * sIn;
    int c0 = blockIdx.x * 32, r0 = blockIdx.y * 32;
    int tx = threadIdx.x, ty = threadIdx.y;
#pragma unroll
    for (int j = 0; j < 4; j++)
        t[ty + 8*j][tx] = ip[(long)(r0 + ty + 8*j) * Cn + c0 + tx];
    __syncthreads();
#pragma unroll
    for (int j = 0; j < 4; j++) {
        float v = t[tx][ty + 8*j];
        __half h, l; fsplit(v, h, l);
        long o = zb * sOut + (long)(c0 + ty + 8*j) * R + r0 + tx;
        oh[o] = h; ol[o] = l;
    }
}

__global__ void softmax_split() {
    int row = blockIdx.x;
    int q = row & (Sc - 1);
    const float* sc = g_scores + (size_t)row * Sc;
    __half* ph_ = g_p_h + (size_t)row * Sc;
    __half* pl_ = g_p_l + (size_t)row * Sc;
    int len = q + 1, tid = threadIdx.x;
    __shared__ float red[8];

    float mx = -1e30f;
    for (int k = tid; k < len; k += 256) mx = fmaxf(mx, sc[k]);
#pragma unroll
    for (int o = 16; o; o >>= 1) mx = fmaxf(mx, __shfl_xor_sync(~0u, mx, o));
    if ((tid & 31) == 0) red[tid >> 5] = mx;
    __syncthreads();
    mx = red[0];
#pragma unroll
    for (int i = 1; i < 8; i++) mx = fmaxf(mx, red[i]);
    __syncthreads();

    float sum = 0.f;
    for (int k = tid; k < len; k += 256) sum += __expf(sc[k] - mx);
#pragma unroll
    for (int o = 16; o; o >>= 1) sum += __shfl_xor_sync(~0u, sum, o);
    if ((tid & 31) == 0) red[tid >> 5] = sum;
    __syncthreads();
    sum = 0.f;
#pragma unroll
    for (int i = 0; i < 8; i++) sum += red[i];
    float inv = 1.f / sum;

    for (int k = tid; k < Sc; k += 256) {
        float p = (k < len) ? __expf(sc[k] - mx) * inv : 0.f;
        __half h, l; fsplit(p, h, l);
        ph_[k] = h; pl_[k] = l;
    }
}

__global__ void layernorm_split(const float* __restrict__ gamma,
                                const float* __restrict__ beta) {
    int row = blockIdx.x, tid = threadIdx.x;
    float4 v = ((const float4*)(g_a + (size_t)row * Dc))[tid];
    __shared__ float red[8];

    float s = v.x + v.y + v.z + v.w;
#pragma unroll
    for (int o = 16; o; o >>= 1) s += __shfl_xor_sync(~0u, s, o);
    if ((tid & 31) == 0) red[tid >> 5] = s;
    __syncthreads();
    s = 0.f;
#pragma unroll
    for (int i = 0; i < 8; i++) s += red[i];
    float mu = s * (1.f / Dc);
    __syncthreads();

    float dx = v.x - mu, dy = v.y - mu, dz = v.z - mu, dw = v.w - mu;
    float qv = dx*dx + dy*dy + dz*dz + dw*dw;
#pragma unroll
    for (int o = 16; o; o >>= 1) qv += __shfl_xor_sync(~0u, qv, o);
    if ((tid & 31) == 0) red[tid >> 5] = qv;
    __syncthreads();
    qv = 0.f;
#pragma unroll
    for (int i = 0; i < 8; i++) qv += red[i];
    float inv = rsqrtf(qv * (1.f / Dc) + 1e-5f);

    float4 gg = ((const float4*)gamma)[tid];
    float4 bb = ((const float4*)beta)[tid];
    float o0 = dx*inv*gg.x + bb.x, o1 = dy*inv*gg.y + bb.y;
    float o2 = dz*inv*gg.z + bb.z, o3 = dw*inv*gg.w + bb.w;
    __half h[4], l[4];
    fsplit(o0, h[0], l[0]); fsplit(o1, h[1], l[1]);
    fsplit(o2, h[2], l[2]); fsplit(o3, h[3], l[3]);
    size_t o = (size_t)row * Dc / 2 + tid * 2;
    ((__half2*)g_xn_h)[o]   = __halves2half2(h[0], h[1]);
    ((__half2*)g_xn_h)[o+1] = __halves2half2(h[2], h[3]);
    ((__half2*)g_xn_l)[o]   = __halves2half2(l[0], l[1]);
    ((__half2*)g_xn_l)[o+1] = __halves2half2(l[2], l[3]);
}

// ======================= launch =======================
#define SYMADDR(p, s) cudaGetSymbolAddress((void**)&p, s)

extern "C" void kernel_launch(void* const* d_in, const int* in_sizes, int n_in,
                              void* d_out, int out_size) {
    const int*   x    = (const int*)  d_in[0];
    const float* sem  = (const float*)d_in[1];
    const float* pos  = (const float*)d_in[2];
    // d_in[3] = F — identity for attention_input='both'; skipped.
    const float* Qw   = (const float*)d_in[4];
    const float* Kw   = (const float*)d_in[5];
    const float* Vw   = (const float*)d_in[6];
    const float* ln_g = (const float*)d_in[7];
    const float* ln_b = (const float*)d_in[8];
    const float* W1   = (const float*)d_in[9];
    const float* b1   = (const float*)d_in[10];
    const float* W2   = (const float*)d_in[11];
    const float* b2   = (const float*)d_in[12];
    float* out = (float*)d_out;

    __half *hh,*hl,*qwh,*qwl,*kwh,*kwl,*vwh,*vwl,*w1h,*w1l,*w2h,*w2l;
    __half *qxh,*qxl,*kxh,*kxl,*vth,*vtl,*pph,*ppl,*xnh,*xnl,*hdh,*hdl;
    float *vx,*scp,*ap;
    SYMADDR(hh,  g_h_h);   SYMADDR(hl,  g_h_l);
    SYMADDR(qwh, g_qwT_h); SYMADDR(qwl, g_qwT_l);
    SYMADDR(kwh, g_kwT_h); SYMADDR(kwl, g_kwT_l);
    SYMADDR(vwh, g_vwT_h); SYMADDR(vwl, g_vwT_l);
    SYMADDR(w1h, g_w1T_h); SYMADDR(w1l, g_w1T_l);
    SYMADDR(w2h, g_w2T_h); SYMADDR(w2l, g_w2T_l);
    SYMADDR(qxh, g_qx_h);  SYMADDR(qxl, g_qx_l);
    SYMADDR(kxh, g_kx_h);  SYMADDR(kxl, g_kx_l);
    SYMADDR(vx,  g_vx);
    SYMADDR(vth, g_vxT_h); SYMADDR(vtl, g_vxT_l);
    SYMADDR(scp, g_scores);
    SYMADDR(pph, g_p_h);   SYMADDR(ppl, g_p_l);
    SYMADDR(ap,  g_a);
    SYMADDR(xnh, g_xn_h);  SYMADDR(xnl, g_xn_l);
    SYMADDR(hdh, g_hid_h); SYMADDR(hdl, g_hid_l);

    cudaFuncSetAttribute(hmma_gemm<false>, cudaFuncAttributeMaxDynamicSharedMemorySize, GSMEM_BYTES);
    cudaFuncSetAttribute(hmma_gemm<true >, cudaFuncAttributeMaxDynamicSharedMemorySize, GSMEM_BYTES);

    dim3 tb(32, 8);
    // weight transposes + split ([K][N] fp32 -> [N][K] fp16 hi/lo)
    transpose_split<<<dim3(Dc/32, Dc/32, 1), tb>>>(Qw, qwh, qwl, Dc, Dc, 0, 0);
    transpose_split<<<dim3(Dc/32, Dc/32, 1), tb>>>(Kw, kwh, kwl, Dc, Dc, 0, 0);
    transpose_split<<<dim3(Dc/32, Dc/32, 1), tb>>>(Vw, vwh, vwl, Dc, Dc, 0, 0);
    transpose_split<<<dim3(Hc/32, Dc/32, 1), tb>>>(W1, w1h, w1l, Dc, Hc, 0, 0);
    transpose_split<<<dim3(Cc/32, Hc/32, 1), tb>>>(W2, w2h, w2l, Hc, Cc, 0, 0);

    // embeddings (fp32 -> hi/lo)
    embed_split<<<(Mrows * (Dc/4)) / 256, 256>>>(x, (const float4*)sem,
                                                 (const float4*)pos);

    // QKV projections: 2-product (h split, weights hi-only), BN=128
    const int gQKV = (Mrows/128) * (Dc/128);
    hmma_gemm<true><<<gQKV, 256, GSMEM_BYTES>>>(
        hh, hl, qwh, qwl, nullptr, nullptr, qxh, qxl,
        Dc, Dc, Dc, 0, 0, 0, 1.f, F_SWIZ);
    hmma_gemm<true><<<gQKV, 256, GSMEM_BYTES>>>(
        hh, hl, kwh, kwl, nullptr, nullptr, kxh, kxl,
        Dc, Dc, Dc, 0, 0, 0, 1.f, F_SWIZ);
    hmma_gemm<true><<<gQKV, 256, GSMEM_BYTES>>>(
        hh, hl, vwh, vwl, nullptr, vx, nullptr, nullptr,
        Dc, Dc, Dc, 0, 0, 0, 1.f, F_SWIZ);

    // Vx -> VxT hi/lo (per batch [Sc][Dc] -> [Dc][Sc])
    transpose_split<<<dim3(Dc/32, Sc/32, Bc), tb>>>(
        vx, vth, vtl, Sc, Dc, (long)Sc*Dc, (long)Dc*Sc);

    // scores = Qx @ Kx^T / 32, 3-product, causal tile-skip, batched
    hmma_gemm<false><<<dim3(Sc/128, Sc/128, Bc), 256, GSMEM_BYTES>>>(
        qxh, qxl, kxh, kxl, nullptr, scp, nullptr, nullptr,
        Sc, Dc, Dc, (long)Sc*Dc, (long)Sc*Dc, (long)Sc*Sc, 0.03125f, F_CAUSAL);

    // softmax -> probs hi/lo
    softmax_split<<<Bc * Sc, 256>>>();

    // a = probs @ Vx, 3-product, causal K-limit (stride Sc preserved), batched
    hmma_gemm<false><<<dim3(Dc/128, Sc/128, Bc), 256, GSMEM_BYTES>>>(
        pph, ppl, vth, vtl, nullptr, ap, nullptr, nullptr,
        Dc, Sc, Sc, (long)Sc*Sc, (long)Dc*Sc, (long)Sc*Dc, 1.f, F_CAUSALK);

    // LayerNorm -> xn hi/lo
    layernorm_split<<<Mrows, 256>>>(ln_g, ln_b);

    // hidden = relu(xn @ W1 + b1), 2-product, BN=128
    hmma_gemm<true><<<(Mrows/128)*(Hc/128), 256, GSMEM_BYTES>>>(
        xnh, xnl, w1h, w1l, b1, nullptr, hdh, hdl,
        Hc, Dc, Dc, 0, 0, 0, 1.f, F_RELU | F_BIAS | F_SWIZ);

    // out = hidden @ W2 + b2, 2-product, BN=128 (dominant GEMM)
    hmma_gemm<true><<<(Mrows/128)*(Cc/128), 256, GSMEM_BYTES>>>(
        hdh, hdl, w2h, w2l, b2, out, nullptr, nullptr,
        Cc, Hc, Hc, 0, 0, 0, 1.f, F_BIAS | F_SWIZ);
}

// round 14
// speedup vs baseline: 1.6429x; 1.5672x over previous
#include <cuda_runtime.h>
#include <cuda_fp16.h>
#include <cstdint>

// Problem constants
#define Bc 4
#define Sc 2048
#define Dc 1024
#define Hc 4096
#define Cc 32000
#define Mrows (Bc*Sc)   // 8192

// runtime flag bits
#define F_RELU    1
#define F_BIAS    2
#define F_CAUSAL  4
#define F_SWIZ    8
#define F_CAUSALK 16

// ======================= static scratch (no allocs) =======================
__device__ __half g_h_h[(size_t)Mrows*Dc],  g_h_l[(size_t)Mrows*Dc];
__device__ __half g_qwT_h[(size_t)Dc*Dc],   g_qwT_l[(size_t)Dc*Dc];
__device__ __half g_kwT_h[(size_t)Dc*Dc],   g_kwT_l[(size_t)Dc*Dc];
__device__ __half g_vwT_h[(size_t)Dc*Dc],   g_vwT_l[(size_t)Dc*Dc];
__device__ __half g_w1T_h[(size_t)Dc*Hc],   g_w1T_l[(size_t)Dc*Hc];
__device__ __half g_w2T_h[(size_t)Hc*Cc],   g_w2T_l[(size_t)Hc*Cc];
__device__ __half g_qx_h[(size_t)Mrows*Dc], g_qx_l[(size_t)Mrows*Dc];
__device__ __half g_kx_h[(size_t)Mrows*Dc], g_kx_l[(size_t)Mrows*Dc];
__device__ float  g_vx[(size_t)Mrows*Dc];
__device__ __half g_vxT_h[(size_t)Mrows*Dc],g_vxT_l[(size_t)Mrows*Dc]; // [b][Dc][Sc]
__device__ float  g_scores[(size_t)Bc*Sc*Sc];
__device__ __half g_p_h[(size_t)Bc*Sc*Sc],  g_p_l[(size_t)Bc*Sc*Sc];
__device__ float  g_a[(size_t)Mrows*Dc];
__device__ __half g_xn_h[(size_t)Mrows*Dc], g_xn_l[(size_t)Mrows*Dc];
__device__ __half g_hid_h[(size_t)Mrows*Hc],g_hid_l[(size_t)Mrows*Hc];

// ======================= helpers =======================
__device__ __forceinline__ uint32_t smem_u32(const void* p) {
    uint32_t a;
    asm("{ .reg .u64 t; cvta.to.shared.u64 t, %1; cvt.u32.u64 %0, t; }"
        : "=r"(a) : "l"(p));
    return a;
}
__device__ __forceinline__ void cp16(uint32_t dst, const void* src) {
    asm volatile("cp.async.cg.shared.global [%0], [%1], 16;"
                 :: "r"(dst), "l"(src) : "memory");
}
__device__ __forceinline__ void ldm4(uint32_t* r, uint32_t addr) {
    asm volatile("ldmatrix.sync.aligned.m8n8.x4.shared.b16 {%0,%1,%2,%3}, [%4];"
                 : "=r"(r[0]), "=r"(r[1]), "=r"(r[2]), "=r"(r[3]) : "r"(addr));
}
__device__ __forceinline__ void mma16816(float* c, const uint32_t* a, const uint32_t* b) {
    asm volatile(
        "mma.sync.aligned.m16n8k16.row.col.f32.f16.f16.f32 "
        "{%0,%1,%2,%3}, {%4,%5,%6,%7}, {%8,%9}, {%0,%1,%2,%3};"
        : "+f"(c[0]), "+f"(c[1]), "+f"(c[2]), "+f"(c[3])
        : "r"(a[0]), "r"(a[1]), "r"(a[2]), "r"(a[3]), "r"(b[0]), "r"(b[1]));
}
__device__ __forceinline__ void fsplit(float v, __half& h, __half& l) {
    h = __float2half(v);
    l = __float2half(v - __half2float(h));
}

// ======================= HMMA split-fp16 GEMM =======================
// C[M,N] = alpha*(A @ B^T) [+bias][relu].
// A: [M][Ks] fp16 hi/lo rows (first Kd used). B: [N][Ks] fp16 hi/lo rows.
// Kd = K extent (clamped by F_CAUSALK); Ks = row STRIDE (never clamped).
// NPROD=3: Ah*Bh + Ah*Bl + Al*Bh  (residual ~2^-22)
// NPROD=2: Ah*Bh + Al*Bh          (B hi-only; residual ~2^-12 scaled)
// NPROD=1: Ah*Bh                  (both hi-only; + A-rounding ~1.4e-4)
// CTA tile 128x128, 8 warps (2m x 4n, warp 64x32), BK=32, 3-stage cp.async.
// Smem row = 128B: [hi k0..31 | lo k0..31], chunk-xor swizzle.
// Output: fp32 (Cf != nullptr) or fp16 hi/lo split (Ch/Cl).
#define NSTAGE 3
#define SSTRIDE 32768           // 16KB A + 16KB B per stage
#define GSMEM_BYTES (NSTAGE*SSTRIDE)

template<int NPROD>
__global__ void __launch_bounds__(256)
hmma_gemm(const __half* __restrict__ Ah, const __half* __restrict__ Al,
          const __half* __restrict__ Bh, const __half* __restrict__ Bl,
          const float* __restrict__ bias,
          float* __restrict__ Cf,
          __half* __restrict__ Ch, __half* __restrict__ Cl,
          int Nd, int Kd, int Ks, long sA, long sB, long sC,
          float alpha, int flags)
{
    int m_tile, n_tile;
    if (flags & F_SWIZ) {             // L2-aware 1D swizzle, GROUP_M = 8
        const int numN = Nd >> 7;
        const int pid = blockIdx.x;
        const int grp = 8 * numN;
        const int gid = pid / grp;
        m_tile = gid * 8 + (pid % 8);
        n_tile = (pid % grp) / 8;
    } else {
        m_tile = blockIdx.y;
        n_tile = blockIdx.x;
    }
    if ((flags & F_CAUSAL) && n_tile > m_tile) return;
    const int m0 = m_tile * 128, n0 = n_tile * 128;
    if (flags & F_CAUSALK) { const int kl = (m_tile + 1) * 128; if (kl < Kd) Kd = kl; }

    extern __shared__ char smem[];
    const uint32_t sbase = smem_u32(smem);

    const int tid = threadIdx.x, wid = tid >> 5, lid = tid & 31;
    const int wm = wid >> 2, wn = wid & 3;           // warp 2m x 4n
    const int mi = lid >> 3, r8 = lid & 7;           // ldmatrix lane roles

    Ah += blockIdx.z * sA;  Al += blockIdx.z * sA;
    Bh += blockIdx.z * sB;  Bl += blockIdx.z * sB;
    if (Cf) { Cf += blockIdx.z * sC; }
    else    { Ch += blockIdx.z * sC; Cl += blockIdx.z * sC; }

    // ---- stage loader. A lo loaded iff NPROD>=2; B lo iff NPROD==3. ----
    // Addresses use Ks (stride); loop extent uses Kd.
    auto stage_load = [&](int kc, int st) {
        const uint32_t sa = sbase + st * SSTRIDE;
        const uint32_t sbB = sa + 16384;
#pragma unroll
        for (int jj = 0; jj < 4; jj++) {
            const int idx = tid + jj * 256;
            const int row = idx >> 3, c = idx & 7;   // c: 0-3 hi, 4-7 lo
            const uint32_t sw = (uint32_t)((c ^ (row & 7)) << 4);
            const long ge = (long)kc * 32 + (c & 3) * 8;
            if (NPROD >= 2 || c < 4) {
                const __half* gA = (c < 4 ? Ah : Al) + (long)(m0 + row) * Ks + ge;
                cp16(sa + row * 128 + sw, gA);
            }
            if (NPROD == 3 || c < 4) {
                const __half* gB = (c < 4 ? Bh : Bl) + (long)(n0 + row) * Ks + ge;
                cp16(sbB + row * 128 + sw, gB);
            }
        }
        asm volatile("cp.async.commit_group;" ::: "memory");
    };

    float acc[4][4][4];
#pragma unroll
    for (int i = 0; i < 4; i++)
#pragma unroll
        for (int j = 0; j < 4; j++)
#pragma unroll
            for (int r = 0; r < 4; r++) acc[i][j][r] = 0.f;

    const int ntiles = Kd >> 5;
    stage_load(0, 0);
    stage_load(1, 1);

    for (int t = 0; t < ntiles; t++) {
        if (t + 1 < ntiles) asm volatile("cp.async.wait_group 1;" ::: "memory");
        else                asm volatile("cp.async.wait_group 0;" ::: "memory");
        __syncthreads();
        if (t + 2 < ntiles) stage_load(t + 2, (t + 2) % NSTAGE);

        const uint32_t Ab = sbase + (t % NSTAGE) * SSTRIDE;
        const uint32_t Bb = Ab + 16384;
#pragma unroll
        for (int ks = 0; ks < 2; ks++) {
            uint32_t a[2][4][4], b[2][4][2];
#pragma unroll
            for (int type = 0; type < 2; type++) {
                const int chunk = type * 4 + ks * 2 + (mi >> 1);
                if (NPROD >= 2 || type == 0) {
#pragma unroll
                    for (int i = 0; i < 4; i++) {     // A: hi (type0) + lo (type1)
                        const int row = wm * 64 + i * 16 + (mi & 1) * 8 + r8;
                        ldm4(a[type][i], Ab + row * 128 + (((chunk ^ (row & 7))) << 4));
                    }
                }
                if (NPROD == 3 || type == 0) {
#pragma unroll
                    for (int jj = 0; jj < 2; jj++) {  // B: 2 x (two n8 tiles)
                        const int row = wn * 32 + jj * 16 + (mi & 1) * 8 + r8;
                        uint32_t r4[4];
                        ldm4(r4, Bb + row * 128 + (((chunk ^ (row & 7))) << 4));
                        b[type][jj*2  ][0] = r4[0]; b[type][jj*2+1][0] = r4[1];
                        b[type][jj*2  ][1] = r4[2]; b[type][jj*2+1][1] = r4[3];
                    }
                }
            }
            // products
#pragma unroll
            for (int i = 0; i < 4; i++)
#pragma unroll
                for (int j = 0; j < 4; j++) mma16816(acc[i][j], a[0][i], b[0][j]);   // hi*hi
            if (NPROD >= 2) {
#pragma unroll
                for (int i = 0; i < 4; i++)
#pragma unroll
                    for (int j = 0; j < 4; j++) mma16816(acc[i][j], a[1][i], b[0][j]); // lo*hi
            }
            if (NPROD == 3) {
#pragma unroll
                for (int i = 0; i < 4; i++)
#pragma unroll
                    for (int j = 0; j < 4; j++) mma16816(acc[i][j], a[0][i], b[1][j]); // hi*lo
            }
        }
        __syncthreads();
    }

    // ---- epilogue: per thread, 2 rows x 2 cols per (i,j) fragment ----
    const int g = lid >> 2, tq = lid & 3;
    const bool do_bias = (flags & F_BIAS), do_relu = (flags & F_RELU);
#pragma unroll
    for (int i = 0; i < 4; i++) {
        const int row0 = m0 + wm * 64 + i * 16 + g;
#pragma unroll
        for (int j = 0; j < 4; j++) {
            const int col = n0 + wn * 32 + j * 8 + tq * 2;
            float v0 = acc[i][j][0] * alpha, v1 = acc[i][j][1] * alpha;
            float v2 = acc[i][j][2] * alpha, v3 = acc[i][j][3] * alpha;
            if (do_bias) {
                const float b0 = bias[col], b1 = bias[col + 1];
                v0 += b0; v1 += b1; v2 += b0; v3 += b1;
            }
            if (do_relu) {
                v0 = fmaxf(v0, 0.f); v1 = fmaxf(v1, 0.f);
                v2 = fmaxf(v2, 0.f); v3 = fmaxf(v3, 0.f);
            }
            if (Cf) {
                *(float2*)(Cf + (long)row0 * Nd + col)       = make_float2(v0, v1);
                *(float2*)(Cf + (long)(row0 + 8) * Nd + col) = make_float2(v2, v3);
            } else {
                __half h0,l0,h1,l1,h2,l2,h3,l3;
                fsplit(v0,h0,l0); fsplit(v1,h1,l1); fsplit(v2,h2,l2); fsplit(v3,h3,l3);
                *(__half2*)(Ch + (long)row0 * Nd + col)       = __halves2half2(h0, h1);
                *(__half2*)(Cl + (long)row0 * Nd + col)       = __halves2half2(l0, l1);
                *(__half2*)(Ch + (long)(row0 + 8) * Nd + col) = __halves2half2(h2, h3);
                *(__half2*)(Cl + (long)(row0 + 8) * Nd + col) = __halves2half2(l2, l3);
            }
        }
    }
}

// ======================= aux kernels =======================
__global__ void embed_split(const int* __restrict__ x,
                            const float4* __restrict__ sem,
                            const float4* __restrict__ pos) {
    const int D4 = Dc / 4;
    int idx = blockIdx.x * 256 + threadIdx.x;
    int m = idx / D4, d4 = idx - m * D4;
    float4 a = sem[(size_t)x[m] * D4 + d4];
    float4 p = pos[(size_t)(m & (Sc - 1)) * D4 + d4];
    float v[4] = {a.x + p.x, a.y + p.y, a.z + p.z, a.w + p.w};
    __half h[4], l[4];
#pragma unroll
    for (int j = 0; j < 4; j++) fsplit(v[j], h[j], l[j]);
    __half2* oh = (__half2*)g_h_h + (size_t)idx * 2;
    __half2* ol = (__half2*)g_h_l + (size_t)idx * 2;
    oh[0] = __halves2half2(h[0], h[1]); oh[1] = __halves2half2(h[2], h[3]);
    ol[0] = __halves2half2(l[0], l[1]); ol[1] = __halves2half2(l[2], l[3]);
}

__global__ void transpose_split(const float* __restrict__ in,
                                __half* __restrict__ oh,
                                __half* __restrict__ ol,
                                int R, int Cn, long sIn, long sOut) {
    __shared__ float t[32][33];
    const long zb = blockIdx.z;
    const float* ip = in + zb * sIn;
    int c0 = blockIdx.x * 32, r0 = blockIdx.y * 32;
    int tx = threadIdx.x, ty = threadIdx.y;
#pragma unroll
    for (int j = 0; j < 4; j++)
        t[ty + 8*j][tx] = ip[(long)(r0 + ty + 8*j) * Cn + c0 + tx];
    __syncthreads();
#pragma unroll
    for (int j = 0; j < 4; j++) {
        float v = t[tx][ty + 8*j];
        __half h, l; fsplit(v, h, l);
        long o = zb * sOut + (long)(c0 + ty + 8*j) * R + r0 + tx;
        oh[o] = h; ol[o] = l;
    }
}

__global__ void softmax_split() {
    int row = blockIdx.x;
    int q = row & (Sc - 1);
    const float* sc = g_scores + (size_t)row * Sc;
    __half* ph_ = g_p_h + (size_t)row * Sc;
    __half* pl_ = g_p_l + (size_t)row * Sc;
    int len = q + 1, tid = threadIdx.x;
    __shared__ float red[8];

    float mx = -1e30f;
    for (int k = tid; k < len; k += 256) mx = fmaxf(mx, sc[k]);
#pragma unroll
    for (int o = 16; o; o >>= 1) mx = fmaxf(mx, __shfl_xor_sync(~0u, mx, o));
    if ((tid & 31) == 0) red[tid >> 5] = mx;
    __syncthreads();
    mx = red[0];
#pragma unroll
    for (int i = 1; i < 8; i++) mx = fmaxf(mx, red[i]);
    __syncthreads();

    float sum = 0.f;
    for (int k = tid; k < len; k += 256) sum += __expf(sc[k] - mx);
#pragma unroll
    for (int o = 16; o; o >>= 1) sum += __shfl_xor_sync(~0u, sum, o);
    if ((tid & 31) == 0) red[tid >> 5] = sum;
    __syncthreads();
    sum = 0.f;
#pragma unroll
    for (int i = 0; i < 8; i++) sum += red[i];
    float inv = 1.f / sum;

    for (int k = tid; k < Sc; k += 256) {
        float p = (k < len) ? __expf(sc[k] - mx) * inv : 0.f;
        __half h, l; fsplit(p, h, l);
        ph_[k] = h; pl_[k] = l;
    }
}

__global__ void layernorm_split(const float* __restrict__ gamma,
                                const float* __restrict__ beta) {
    int row = blockIdx.x, tid = threadIdx.x;
    float4 v = ((const float4*)(g_a + (size_t)row * Dc))[tid];
    __shared__ float red[8];

    float s = v.x + v.y + v.z + v.w;
#pragma unroll
    for (int o = 16; o; o >>= 1) s += __shfl_xor_sync(~0u, s, o);
    if ((tid & 31) == 0) red[tid >> 5] = s;
    __syncthreads();
    s = 0.f;
#pragma unroll
    for (int i = 0; i < 8; i++) s += red[i];
    float mu = s * (1.f / Dc);
    __syncthreads();

    float dx = v.x - mu, dy = v.y - mu, dz = v.z - mu, dw = v.w - mu;
    float qv = dx*dx + dy*dy + dz*dz + dw*dw;
#pragma unroll
    for (int o = 16; o; o >>= 1) qv += __shfl_xor_sync(~0u, qv, o);
    if ((tid & 31) == 0) red[tid >> 5] = qv;
    __syncthreads();
    qv = 0.f;
#pragma unroll
    for (int i = 0; i < 8; i++) qv += red[i];
    float inv = rsqrtf(qv * (1.f / Dc) + 1e-5f);

    float4 gg = ((const float4*)gamma)[tid];
    float4 bb = ((const float4*)beta)[tid];
    float o0 = dx*inv*gg.x + bb.x, o1 = dy*inv*gg.y + bb.y;
    float o2 = dz*inv*gg.z + bb.z, o3 = dw*inv*gg.w + bb.w;
    __half h[4], l[4];
    fsplit(o0, h[0], l[0]); fsplit(o1, h[1], l[1]);
    fsplit(o2, h[2], l[2]); fsplit(o3, h[3], l[3]);
    size_t o = (size_t)row * Dc / 2 + tid * 2;
    ((__half2*)g_xn_h)[o]   = __halves2half2(h[0], h[1]);
    ((__half2*)g_xn_h)[o+1] = __halves2half2(h[2], h[3]);
    ((__half2*)g_xn_l)[o]   = __halves2half2(l[0], l[1]);
    ((__half2*)g_xn_l)[o+1] = __halves2half2(l[2], l[3]);
}

// ======================= launch =======================
#define SYMADDR(p, s) cudaGetSymbolAddress((void**)&p, s)

extern "C" void kernel_launch(void* const* d_in, const int* in_sizes, int n_in,
                              void* d_out, int out_size) {
    const int*   x    = (const int*)  d_in[0];
    const float* sem  = (const float*)d_in[1];
    const float* pos  = (const float*)d_in[2];
    // d_in[3] = F — identity for attention_input='both'; skipped.
    const float* Qw   = (const float*)d_in[4];
    const float* Kw   = (const float*)d_in[5];
    const float* Vw   = (const float*)d_in[6];
    const float* ln_g = (const float*)d_in[7];
    const float* ln_b = (const float*)d_in[8];
    const float* W1   = (const float*)d_in[9];
    const float* b1   = (const float*)d_in[10];
    const float* W2   = (const float*)d_in[11];
    const float* b2   = (const float*)d_in[12];
    float* out = (float*)d_out;

    __half *hh,*hl,*qwh,*qwl,*kwh,*kwl,*vwh,*vwl,*w1h,*w1l,*w2h,*w2l;
    __half *qxh,*qxl,*kxh,*kxl,*vth,*vtl,*pph,*ppl,*xnh,*xnl,*hdh,*hdl;
    float *vx,*scp,*ap;
    SYMADDR(hh,  g_h_h);   SYMADDR(hl,  g_h_l);
    SYMADDR(qwh, g_qwT_h); SYMADDR(qwl, g_qwT_l);
    SYMADDR(kwh, g_kwT_h); SYMADDR(kwl, g_kwT_l);
    SYMADDR(vwh, g_vwT_h); SYMADDR(vwl, g_vwT_l);
    SYMADDR(w1h, g_w1T_h); SYMADDR(w1l, g_w1T_l);
    SYMADDR(w2h, g_w2T_h); SYMADDR(w2l, g_w2T_l);
    SYMADDR(qxh, g_qx_h);  SYMADDR(qxl, g_qx_l);
    SYMADDR(kxh, g_kx_h);  SYMADDR(kxl, g_kx_l);
    SYMADDR(vx,  g_vx);
    SYMADDR(vth, g_vxT_h); SYMADDR(vtl, g_vxT_l);
    SYMADDR(scp, g_scores);
    SYMADDR(pph, g_p_h);   SYMADDR(ppl, g_p_l);
    SYMADDR(ap,  g_a);
    SYMADDR(xnh, g_xn_h);  SYMADDR(xnl, g_xn_l);
    SYMADDR(hdh, g_hid_h); SYMADDR(hdl, g_hid_l);

    cudaFuncSetAttribute(hmma_gemm<3>, cudaFuncAttributeMaxDynamicSharedMemorySize, GSMEM_BYTES);
    cudaFuncSetAttribute(hmma_gemm<2>, cudaFuncAttributeMaxDynamicSharedMemorySize, GSMEM_BYTES);
    cudaFuncSetAttribute(hmma_gemm<1>, cudaFuncAttributeMaxDynamicSharedMemorySize, GSMEM_BYTES);

    dim3 tb(32, 8);
    // weight transposes + split ([K][N] fp32 -> [N][K] fp16 hi/lo)
    transpose_split<<<dim3(Dc/32, Dc/32, 1), tb>>>(Qw, qwh, qwl, Dc, Dc, 0, 0);
    transpose_split<<<dim3(Dc/32, Dc/32, 1), tb>>>(Kw, kwh, kwl, Dc, Dc, 0, 0);
    transpose_split<<<dim3(Dc/32, Dc/32, 1), tb>>>(Vw, vwh, vwl, Dc, Dc, 0, 0);
    transpose_split<<<dim3(Hc/32, Dc/32, 1), tb>>>(W1, w1h, w1l, Dc, Hc, 0, 0);
    transpose_split<<<dim3(Cc/32, Hc/32, 1), tb>>>(W2, w2h, w2l, Hc, Cc, 0, 0);

    // embeddings (fp32 -> hi/lo)
    embed_split<<<(Mrows * (Dc/4)) / 256, 256>>>(x, (const float4*)sem,
                                                 (const float4*)pos);

    // QKV projections: 2-product (h split, weights hi-only), BN=128
    const int gQKV = (Mrows/128) * (Dc/128);
    hmma_gemm<2><<<gQKV, 256, GSMEM_BYTES>>>(
        hh, hl, qwh, qwl, nullptr, nullptr, qxh, qxl,
        Dc, Dc, Dc, 0, 0, 0, 1.f, F_SWIZ);
    hmma_gemm<2><<<gQKV, 256, GSMEM_BYTES>>>(
        hh, hl, kwh, kwl, nullptr, nullptr, kxh, kxl,
        Dc, Dc, Dc, 0, 0, 0, 1.f, F_SWIZ);
    hmma_gemm<2><<<gQKV, 256, GSMEM_BYTES>>>(
        hh, hl, vwh, vwl, nullptr, vx, nullptr, nullptr,
        Dc, Dc, Dc, 0, 0, 0, 1.f, F_SWIZ);

    // Vx -> VxT hi/lo (per batch [Sc][Dc] -> [Dc][Sc])
    transpose_split<<<dim3(Dc/32, Sc/32, Bc), tb>>>(
        vx, vth, vtl, Sc, Dc, (long)Sc*Dc, (long)Dc*Sc);

    // scores = Qx @ Kx^T / 32, 3-product, causal tile-skip, batched
    hmma_gemm<3><<<dim3(Sc/128, Sc/128, Bc), 256, GSMEM_BYTES>>>(
        qxh, qxl, kxh, kxl, nullptr, scp, nullptr, nullptr,
        Sc, Dc, Dc, (long)Sc*Dc, (long)Sc*Dc, (long)Sc*Sc, 0.03125f, F_CAUSAL);

    // softmax -> probs hi/lo
    softmax_split<<<Bc * Sc, 256>>>();

    // a = probs @ Vx, 3-product, causal K-limit (stride Sc preserved), batched
    hmma_gemm<3><<<dim3(Dc/128, Sc/128, Bc), 256, GSMEM_BYTES>>>(
        pph, ppl, vth, vtl, nullptr, ap, nullptr, nullptr,
        Dc, Sc, Sc, (long)Sc*Sc, (long)Dc*Sc, (long)Sc*Dc, 1.f, F_CAUSALK);

    // LayerNorm -> xn hi/lo
    layernorm_split<<<Mrows, 256>>>(ln_g, ln_b);

    // hidden = relu(xn @ W1 + b1), 2-product, BN=128
    hmma_gemm<2><<<(Mrows/128)*(Hc/128), 256, GSMEM_BYTES>>>(
        xnh, xnl, w1h, w1l, b1, nullptr, hdh, hdl,
        Hc, Dc, Dc, 0, 0, 0, 1.f, F_RELU | F_BIAS | F_SWIZ);

    // out = hidden @ W2 + b2, SINGLE-product (both hi-only), BN=128
    hmma_gemm<1><<<(Mrows/128)*(Cc/128), 256, GSMEM_BYTES>>>(
        hdh, hdl, w2h, w2l, b2, out, nullptr, nullptr,
        Cc, Hc, Hc, 0, 0, 0, 1.f, F_BIAS | F_SWIZ);
}

// round 15
// speedup vs baseline: 1.6629x; 1.0121x over previous
#include <cuda_runtime.h>
#include <cuda_fp16.h>
#include <cstdint>

// Problem constants
#define Bc 4
#define Sc 2048
#define Dc 1024
#define Hc 4096
#define Cc 32000
#define Mrows (Bc*Sc)   // 8192

// runtime flag bits
#define F_RELU    1
#define F_BIAS    2
#define F_CAUSAL  4
#define F_SWIZ    8
#define F_CAUSALK 16

// ======================= static scratch (no allocs) =======================
__device__ __half g_h_h[(size_t)Mrows*Dc],  g_h_l[(size_t)Mrows*Dc];
__device__ __half g_qwT_h[(size_t)Dc*Dc],   g_qwT_l[(size_t)Dc*Dc];
__device__ __half g_kwT_h[(size_t)Dc*Dc],   g_kwT_l[(size_t)Dc*Dc];
__device__ __half g_vwT_h[(size_t)Dc*Dc],   g_vwT_l[(size_t)Dc*Dc];
__device__ __half g_w1T_h[(size_t)Dc*Hc],   g_w1T_l[(size_t)Dc*Hc];
__device__ __half g_w2T_h[(size_t)Hc*Cc],   g_w2T_l[(size_t)Hc*Cc];
__device__ __half g_qx_h[(size_t)Mrows*Dc], g_qx_l[(size_t)Mrows*Dc];
__device__ __half g_kx_h[(size_t)Mrows*Dc], g_kx_l[(size_t)Mrows*Dc];
__device__ float  g_vx[(size_t)Mrows*Dc];
__device__ __half g_vxT_h[(size_t)Mrows*Dc],g_vxT_l[(size_t)Mrows*Dc]; // [b][Dc][Sc]
__device__ float  g_scores[(size_t)Bc*Sc*Sc];
__device__ __half g_p_h[(size_t)Bc*Sc*Sc],  g_p_l[(size_t)Bc*Sc*Sc];
__device__ float  g_a[(size_t)Mrows*Dc];
__device__ __half g_xn_h[(size_t)Mrows*Dc], g_xn_l[(size_t)Mrows*Dc];
__device__ __half g_hid_h[(size_t)Mrows*Hc],g_hid_l[(size_t)Mrows*Hc];

// ======================= helpers =======================
__device__ __forceinline__ uint32_t smem_u32(const void* p) {
    uint32_t a;
    asm("{ .reg .u64 t; cvta.to.shared.u64 t, %1; cvt.u32.u64 %0, t; }"
        : "=r"(a) : "l"(p));
    return a;
}
__device__ __forceinline__ void cp16(uint32_t dst, const void* src) {
    asm volatile("cp.async.cg.shared.global [%0], [%1], 16;"
                 :: "r"(dst), "l"(src) : "memory");
}
__device__ __forceinline__ void ldm4(uint32_t* r, uint32_t addr) {
    asm volatile("ldmatrix.sync.aligned.m8n8.x4.shared.b16 {%0,%1,%2,%3}, [%4];"
                 : "=r"(r[0]), "=r"(r[1]), "=r"(r[2]), "=r"(r[3]) : "r"(addr));
}
__device__ __forceinline__ void mma16816(float* c, const uint32_t* a, const uint32_t* b) {
    asm volatile(
        "mma.sync.aligned.m16n8k16.row.col.f32.f16.f16.f32 "
        "{%0,%1,%2,%3}, {%4,%5,%6,%7}, {%8,%9}, {%0,%1,%2,%3};"
        : "+f"(c[0]), "+f"(c[1]), "+f"(c[2]), "+f"(c[3])
        : "r"(a[0]), "r"(a[1]), "r"(a[2]), "r"(a[3]), "r"(b[0]), "r"(b[1]));
}
__device__ __forceinline__ void fsplit(float v, __half& h, __half& l) {
    h = __float2half(v);
    l = __float2half(v - __half2float(h));
}

// ======================= HMMA split-fp16 GEMM =======================
// C[M,N] = alpha*(A @ B^T) [+bias][relu].
// A: [M][Ks] fp16 hi/lo rows (first Kd used). B: [N][Ks] fp16 hi/lo rows.
// Kd = K extent (clamped by F_CAUSALK); Ks = row STRIDE (never clamped).
// NPROD=3: Ah*Bh + Ah*Bl + Al*Bh  (residual ~2^-22)
// NPROD=2: Ah*Bh + Al*Bh          (B hi-only; residual ~2^-12 scaled)
// NPROD=1: Ah*Bh                  (both hi-only; + A-rounding ~1.4e-4)
// MINCTA: min blocks/SM (2 for NPROD=1 — caps regs ~124, 2 CTAs co-resident
//         to overlap barrier/smem-latency bubbles; 1 otherwise to avoid spill).
// CTA tile 128x128, 8 warps (2m x 4n, warp 64x32), BK=32, 3-stage cp.async.
// Smem row = 128B: [hi k0..31 | lo k0..31], chunk-xor swizzle.
// Output: fp32 (Cf != nullptr) or fp16 hi/lo split (Ch/Cl).
#define NSTAGE 3
#define SSTRIDE 32768           // 16KB A + 16KB B per stage
#define GSMEM_BYTES (NSTAGE*SSTRIDE)

template<int NPROD, int MINCTA>
__global__ void __launch_bounds__(256, MINCTA)
hmma_gemm(const __half* __restrict__ Ah, const __half* __restrict__ Al,
          const __half* __restrict__ Bh, const __half* __restrict__ Bl,
          const float* __restrict__ bias,
          float* __restrict__ Cf,
          __half* __restrict__ Ch, __half* __restrict__ Cl,
          int Nd, int Kd, int Ks, long sA, long sB, long sC,
          float alpha, int flags)
{
    int m_tile, n_tile;
    if (flags & F_SWIZ) {             // L2-aware 1D swizzle, GROUP_M = 8
        const int numN = Nd >> 7;
        const int pid = blockIdx.x;
        const int grp = 8 * numN;
        const int gid = pid / grp;
        m_tile = gid * 8 + (pid % 8);
        n_tile = (pid % grp) / 8;
    } else {
        m_tile = blockIdx.y;
        n_tile = blockIdx.x;
    }
    if ((flags & F_CAUSAL) && n_tile > m_tile) return;
    const int m0 = m_tile * 128, n0 = n_tile * 128;
    if (flags & F_CAUSALK) { const int kl = (m_tile + 1) * 128; if (kl < Kd) Kd = kl; }

    extern __shared__ char smem[];
    const uint32_t sbase = smem_u32(smem);

    const int tid = threadIdx.x, wid = tid >> 5, lid = tid & 31;
    const int wm = wid >> 2, wn = wid & 3;           // warp 2m x 4n
    const int mi = lid >> 3, r8 = lid & 7;           // ldmatrix lane roles

    Ah += blockIdx.z * sA;  Al += blockIdx.z * sA;
    Bh += blockIdx.z * sB;  Bl += blockIdx.z * sB;
    if (Cf) { Cf += blockIdx.z * sC; }
    else    { Ch += blockIdx.z * sC; Cl += blockIdx.z * sC; }

    // ---- stage loader. A lo loaded iff NPROD>=2; B lo iff NPROD==3. ----
    // Addresses use Ks (stride); loop extent uses Kd.
    auto stage_load = [&](int kc, int st) {
        const uint32_t sa = sbase + st * SSTRIDE;
        const uint32_t sbB = sa + 16384;
#pragma unroll
        for (int jj = 0; jj < 4; jj++) {
            const int idx = tid + jj * 256;
            const int row = idx >> 3, c = idx & 7;   // c: 0-3 hi, 4-7 lo
            const uint32_t sw = (uint32_t)((c ^ (row & 7)) << 4);
            const long ge = (long)kc * 32 + (c & 3) * 8;
            if (NPROD >= 2 || c < 4) {
                const __half* gA = (c < 4 ? Ah : Al) + (long)(m0 + row) * Ks + ge;
                cp16(sa + row * 128 + sw, gA);
            }
            if (NPROD == 3 || c < 4) {
                const __half* gB = (c < 4 ? Bh : Bl) + (long)(n0 + row) * Ks + ge;
                cp16(sbB + row * 128 + sw, gB);
            }
        }
        asm volatile("cp.async.commit_group;" ::: "memory");
    };

    float acc[4][4][4];
#pragma unroll
    for (int i = 0; i < 4; i++)
#pragma unroll
        for (int j = 0; j < 4; j++)
#pragma unroll
            for (int r = 0; r < 4; r++) acc[i][j][r] = 0.f;

    const int ntiles = Kd >> 5;
    stage_load(0, 0);
    stage_load(1, 1);

    for (int t = 0; t < ntiles; t++) {
        if (t + 1 < ntiles) asm volatile("cp.async.wait_group 1;" ::: "memory");
        else                asm volatile("cp.async.wait_group 0;" ::: "memory");
        __syncthreads();
        if (t + 2 < ntiles) stage_load(t + 2, (t + 2) % NSTAGE);

        const uint32_t Ab = sbase + (t % NSTAGE) * SSTRIDE;
        const uint32_t Bb = Ab + 16384;
#pragma unroll
        for (int ks = 0; ks < 2; ks++) {
            uint32_t a[2][4][4], b[2][4][2];
#pragma unroll
            for (int type = 0; type < 2; type++) {
                const int chunk = type * 4 + ks * 2 + (mi >> 1);
                if (NPROD >= 2 || type == 0) {
#pragma unroll
                    for (int i = 0; i < 4; i++) {     // A: hi (type0) + lo (type1)
                        const int row = wm * 64 + i * 16 + (mi & 1) * 8 + r8;
                        ldm4(a[type][i], Ab + row * 128 + (((chunk ^ (row & 7))) << 4));
                    }
                }
                if (NPROD == 3 || type == 0) {
#pragma unroll
                    for (int jj = 0; jj < 2; jj++) {  // B: 2 x (two n8 tiles)
                        const int row = wn * 32 + jj * 16 + (mi & 1) * 8 + r8;
                        uint32_t r4[4];
                        ldm4(r4, Bb + row * 128 + (((chunk ^ (row & 7))) << 4));
                        b[type][jj*2  ][0] = r4[0]; b[type][jj*2+1][0] = r4[1];
                        b[type][jj*2  ][1] = r4[2]; b[type][jj*2+1][1] = r4[3];
                    }
                }
            }
            // products
#pragma unroll
            for (int i = 0; i < 4; i++)
#pragma unroll
                for (int j = 0; j < 4; j++) mma16816(acc[i][j], a[0][i], b[0][j]);   // hi*hi
            if (NPROD >= 2) {
#pragma unroll
                for (int i = 0; i < 4; i++)
#pragma unroll
                    for (int j = 0; j < 4; j++) mma16816(acc[i][j], a[1][i], b[0][j]); // lo*hi
            }
            if (NPROD == 3) {
#pragma unroll
                for (int i = 0; i < 4; i++)
#pragma unroll
                    for (int j = 0; j < 4; j++) mma16816(acc[i][j], a[0][i], b[1][j]); // hi*lo
            }
        }
        __syncthreads();
    }

    // ---- epilogue: per thread, 2 rows x 2 cols per (i,j) fragment ----
    const int g = lid >> 2, tq = lid & 3;
    const bool do_bias = (flags & F_BIAS), do_relu = (flags & F_RELU);
#pragma unroll
    for (int i = 0; i < 4; i++) {
        const int row0 = m0 + wm * 64 + i * 16 + g;
#pragma unroll
        for (int j = 0; j < 4; j++) {
            const int col = n0 + wn * 32 + j * 8 + tq * 2;
            float v0 = acc[i][j][0] * alpha, v1 = acc[i][j][1] * alpha;
            float v2 = acc[i][j][2] * alpha, v3 = acc[i][j][3] * alpha;
            if (do_bias) {
                const float b0 = bias[col], b1 = bias[col + 1];
                v0 += b0; v1 += b1; v2 += b0; v3 += b1;
            }
            if (do_relu) {
                v0 = fmaxf(v0, 0.f); v1 = fmaxf(v1, 0.f);
                v2 = fmaxf(v2, 0.f); v3 = fmaxf(v3, 0.f);
            }
            if (Cf) {
                *(float2*)(Cf + (long)row0 * Nd + col)       = make_float2(v0, v1);
                *(float2*)(Cf + (long)(row0 + 8) * Nd + col) = make_float2(v2, v3);
            } else {
                __half h0,l0,h1,l1,h2,l2,h3,l3;
                fsplit(v0,h0,l0); fsplit(v1,h1,l1); fsplit(v2,h2,l2); fsplit(v3,h3,l3);
                *(__half2*)(Ch + (long)row0 * Nd + col)       = __halves2half2(h0, h1);
                *(__half2*)(Cl + (long)row0 * Nd + col)       = __halves2half2(l0, l1);
                *(__half2*)(Ch + (long)(row0 + 8) * Nd + col) = __halves2half2(h2, h3);
                *(__half2*)(Cl + (long)(row0 + 8) * Nd + col) = __halves2half2(l2, l3);
            }
        }
    }
}

// ======================= aux kernels =======================
__global__ void embed_split(const int* __restrict__ x,
                            const float4* __restrict__ sem,
                            const float4* __restrict__ pos) {
    const int D4 = Dc / 4;
    int idx = blockIdx.x * 256 + threadIdx.x;
    int m = idx / D4, d4 = idx - m * D4;
    float4 a = sem[(size_t)x[m] * D4 + d4];
    float4 p = pos[(size_t)(m & (Sc - 1)) * D4 + d4];
    float v[4] = {a.x + p.x, a.y + p.y, a.z + p.z, a.w + p.w};
    __half h[4], l[4];
#pragma unroll
    for (int j = 0; j < 4; j++) fsplit(v[j], h[j], l[j]);
    __half2* oh = (__half2*)g_h_h + (size_t)idx * 2;
    __half2* ol = (__half2*)g_h_l + (size_t)idx * 2;
    oh[0] = __halves2half2(h[0], h[1]); oh[1] = __halves2half2(h[2], h[3]);
    ol[0] = __halves2half2(l[0], l[1]); ol[1] = __halves2half2(l[2], l[3]);
}

__global__ void transpose_split(const float* __restrict__ in,
                                __half* __restrict__ oh,
                                __half* __restrict__ ol,
                                int R, int Cn, long sIn, long sOut) {
    __shared__ float t[32][33];
    const long zb = blockIdx.z;
    const float* ip = in + zb * sIn;
    int c0 = blockIdx.x * 32, r0 = blockIdx.y * 32;
    int tx = threadIdx.x, ty = threadIdx.y;
#pragma unroll
    for (int j = 0; j < 4; j++)
        t[ty + 8*j][tx] = ip[(long)(r0 + ty + 8*j) * Cn + c0 + tx];
    __syncthreads();
#pragma unroll
    for (int j = 0; j < 4; j++) {
        float v = t[tx][ty + 8*j];
        __half h, l; fsplit(v, h, l);
        long o = zb * sOut + (long)(c0 + ty + 8*j) * R + r0 + tx;
        oh[o] = h; ol[o] = l;
    }
}

__global__ void softmax_split() {
    int row = blockIdx.x;
    int q = row & (Sc - 1);
    const float* sc = g_scores + (size_t)row * Sc;
    __half* ph_ = g_p_h + (size_t)row * Sc;
    __half* pl_ = g_p_l + (size_t)row * Sc;
    int len = q + 1, tid = threadIdx.x;
    __shared__ float red[8];

    float mx = -1e30f;
    for (int k = tid; k < len; k += 256) mx = fmaxf(mx, sc[k]);
#pragma unroll
    for (int o = 16; o; o >>= 1) mx = fmaxf(mx, __shfl_xor_sync(~0u, mx, o));
    if ((tid & 31) == 0) red[tid >> 5] = mx;
    __syncthreads();
    mx = red[0];
#pragma unroll
    for (int i = 1; i < 8; i++) mx = fmaxf(mx, red[i]);
    __syncthreads();

    float sum = 0.f;
    for (int k = tid; k < len; k += 256) sum += __expf(sc[k] - mx);
#pragma unroll
    for (int o = 16; o; o >>= 1) sum += __shfl_xor_sync(~0u, sum, o);
    if ((tid & 31) == 0) red[tid >> 5] = sum;
    __syncthreads();
    sum = 0.f;
#pragma unroll
    for (int i = 0; i < 8; i++) sum += red[i];
    float inv = 1.f / sum;

    for (int k = tid; k < Sc; k += 256) {
        float p = (k < len) ? __expf(sc[k] - mx) * inv : 0.f;
        __half h, l; fsplit(p, h, l);
        ph_[k] = h; pl_[k] = l;
    }
}

__global__ void layernorm_split(const float* __restrict__ gamma,
                                const float* __restrict__ beta) {
    int row = blockIdx.x, tid = threadIdx.x;
    float4 v = ((const float4*)(g_a + (size_t)row * Dc))[tid];
    __shared__ float red[8];

    float s = v.x + v.y + v.z + v.w;
#pragma unroll
    for (int o = 16; o; o >>= 1) s += __shfl_xor_sync(~0u, s, o);
    if ((tid & 31) == 0) red[tid >> 5] = s;
    __syncthreads();
    s = 0.f;
#pragma unroll
    for (int i = 0; i < 8; i++) s += red[i];
    float mu = s * (1.f / Dc);
    __syncthreads();

    float dx = v.x - mu, dy = v.y - mu, dz = v.z - mu, dw = v.w - mu;
    float qv = dx*dx + dy*dy + dz*dz + dw*dw;
#pragma unroll
    for (int o = 16; o; o >>= 1) qv += __shfl_xor_sync(~0u, qv, o);
    if ((tid & 31) == 0) red[tid >> 5] = qv;
    __syncthreads();
    qv = 0.f;
#pragma unroll
    for (int i = 0; i < 8; i++) qv += red[i];
    float inv = rsqrtf(qv * (1.f / Dc) + 1e-5f);

    float4 gg = ((const float4*)gamma)[tid];
    float4 bb = ((const float4*)beta)[tid];
    float o0 = dx*inv*gg.x + bb.x, o1 = dy*inv*gg.y + bb.y;
    float o2 = dz*inv*gg.z + bb.z, o3 = dw*inv*gg.w + bb.w;
    __half h[4], l[4];
    fsplit(o0, h[0], l[0]); fsplit(o1, h[1], l[1]);
    fsplit(o2, h[2], l[2]); fsplit(o3, h[3], l[3]);
    size_t o = (size_t)row * Dc / 2 + tid * 2;
    ((__half2*)g_xn_h)[o]   = __halves2half2(h[0], h[1]);
    ((__half2*)g_xn_h)[o+1] = __halves2half2(h[2], h[3]);
    ((__half2*)g_xn_l)[o]   = __halves2half2(l[0], l[1]);
    ((__half2*)g_xn_l)[o+1] = __halves2half2(l[2], l[3]);
}

// ======================= launch =======================
#define SYMADDR(p, s) cudaGetSymbolAddress((void**)&p, s)

extern "C" void kernel_launch(void* const* d_in, const int* in_sizes, int n_in,
                              void* d_out, int out_size) {
    const int*   x    = (const int*)  d_in[0];
    const float* sem  = (const float*)d_in[1];
    const float* pos  = (const float*)d_in[2];
    // d_in[3] = F — identity for attention_input='both'; skipped.
    const float* Qw   = (const float*)d_in[4];
    const float* Kw   = (const float*)d_in[5];
    const float* Vw   = (const float*)d_in[6];
    const float* ln_g = (const float*)d_in[7];
    const float* ln_b = (const float*)d_in[8];
    const float* W1   = (const float*)d_in[9];
    const float* b1   = (const float*)d_in[10];
    const float* W2   = (const float*)d_in[11];
    const float* b2   = (const float*)d_in[12];
    float* out = (float*)d_out;

    __half *hh,*hl,*qwh,*qwl,*kwh,*kwl,*vwh,*vwl,*w1h,*w1l,*w2h,*w2l;
    __half *qxh,*qxl,*kxh,*kxl,*vth,*vtl,*pph,*ppl,*xnh,*xnl,*hdh,*hdl;
    float *vx,*scp,*ap;
    SYMADDR(hh,  g_h_h);   SYMADDR(hl,  g_h_l);
    SYMADDR(qwh, g_qwT_h); SYMADDR(qwl, g_qwT_l);
    SYMADDR(kwh, g_kwT_h); SYMADDR(kwl, g_kwT_l);
    SYMADDR(vwh, g_vwT_h); SYMADDR(vwl, g_vwT_l);
    SYMADDR(w1h, g_w1T_h); SYMADDR(w1l, g_w1T_l);
    SYMADDR(w2h, g_w2T_h); SYMADDR(w2l, g_w2T_l);
    SYMADDR(qxh, g_qx_h);  SYMADDR(qxl, g_qx_l);
    SYMADDR(kxh, g_kx_h);  SYMADDR(kxl, g_kx_l);
    SYMADDR(vx,  g_vx);
    SYMADDR(vth, g_vxT_h); SYMADDR(vtl, g_vxT_l);
    SYMADDR(scp, g_scores);
    SYMADDR(pph, g_p_h);   SYMADDR(ppl, g_p_l);
    SYMADDR(ap,  g_a);
    SYMADDR(xnh, g_xn_h);  SYMADDR(xnl, g_xn_l);
    SYMADDR(hdh, g_hid_h); SYMADDR(hdl, g_hid_l);

    cudaFuncSetAttribute(hmma_gemm<3,1>, cudaFuncAttributeMaxDynamicSharedMemorySize, GSMEM_BYTES);
    cudaFuncSetAttribute(hmma_gemm<2,1>, cudaFuncAttributeMaxDynamicSharedMemorySize, GSMEM_BYTES);
    cudaFuncSetAttribute(hmma_gemm<1,2>, cudaFuncAttributeMaxDynamicSharedMemorySize, GSMEM_BYTES);

    dim3 tb(32, 8);
    // weight transposes + split ([K][N] fp32 -> [N][K] fp16 hi/lo)
    transpose_split<<<dim3(Dc/32, Dc/32, 1), tb>>>(Qw, qwh, qwl, Dc, Dc, 0, 0);
    transpose_split<<<dim3(Dc/32, Dc/32, 1), tb>>>(Kw, kwh, kwl, Dc, Dc, 0, 0);
    transpose_split<<<dim3(Dc/32, Dc/32, 1), tb>>>(Vw, vwh, vwl, Dc, Dc, 0, 0);
    transpose_split<<<dim3(Hc/32, Dc/32, 1), tb>>>(W1, w1h, w1l, Dc, Hc, 0, 0);
    transpose_split<<<dim3(Cc/32, Hc/32, 1), tb>>>(W2, w2h, w2l, Hc, Cc, 0, 0);

    // embeddings (fp32 -> hi/lo)
    embed_split<<<(Mrows * (Dc/4)) / 256, 256>>>(x, (const float4*)sem,
                                                 (const float4*)pos);

    // QKV projections: 2-product (h split, weights hi-only), BN=128
    const int gQKV = (Mrows/128) * (Dc/128);
    hmma_gemm<2,1><<<gQKV, 256, GSMEM_BYTES>>>(
        hh, hl, qwh, qwl, nullptr, nullptr, qxh, qxl,
        Dc, Dc, Dc, 0, 0, 0, 1.f, F_SWIZ);
    hmma_gemm<2,1><<<gQKV, 256, GSMEM_BYTES>>>(
        hh, hl, kwh, kwl, nullptr, nullptr, kxh, kxl,
        Dc, Dc, Dc, 0, 0, 0, 1.f, F_SWIZ);
    hmma_gemm<2,1><<<gQKV, 256, GSMEM_BYTES>>>(
        hh, hl, vwh, vwl, nullptr, vx, nullptr, nullptr,
        Dc, Dc, Dc, 0, 0, 0, 1.f, F_SWIZ);

    // Vx -> VxT hi/lo (per batch [Sc][Dc] -> [Dc][Sc])
    transpose_split<<<dim3(Dc/32, Sc/32, Bc), tb>>>(
        vx, vth, vtl, Sc, Dc, (long)Sc*Dc, (long)Dc*Sc);

    // scores = Qx @ Kx^T / 32, 3-product, causal tile-skip, batched
    hmma_gemm<3,1><<<dim3(Sc/128, Sc/128, Bc), 256, GSMEM_BYTES>>>(
        qxh, qxl, kxh, kxl, nullptr, scp, nullptr, nullptr,
        Sc, Dc, Dc, (long)Sc*Dc, (long)Sc*Dc, (long)Sc*Sc, 0.03125f, F_CAUSAL);

    // softmax -> probs hi/lo
    softmax_split<<<Bc * Sc, 256>>>();

    // a = probs @ Vx, 3-product, causal K-limit (stride Sc preserved), batched
    hmma_gemm<3,1><<<dim3(Dc/128, Sc/128, Bc), 256, GSMEM_BYTES>>>(
        pph, ppl, vth, vtl, nullptr, ap, nullptr, nullptr,
        Dc, Sc, Sc, (long)Sc*Sc, (long)Dc*Sc, (long)Sc*Dc, 1.f, F_CAUSALK);

    // LayerNorm -> xn hi/lo
    layernorm_split<<<Mrows, 256>>>(ln_g, ln_b);

    // hidden = relu(xn @ W1 + b1), 2-product, BN=128
    hmma_gemm<2,1><<<(Mrows/128)*(Hc/128), 256, GSMEM_BYTES>>>(
        xnh, xnl, w1h, w1l, b1, nullptr, hdh, hdl,
        Hc, Dc, Dc, 0, 0, 0, 1.f, F_RELU | F_BIAS | F_SWIZ);

    // out = hidden @ W2 + b2, SINGLE-product, 2 CTAs/SM (dominant GEMM)
    hmma_gemm<1,2><<<(Mrows/128)*(Cc/128), 256, GSMEM_BYTES>>>(
        hdh, hdl, w2h, w2l, b2, out, nullptr, nullptr,
        Cc, Hc, Hc, 0, 0, 0, 1.f, F_BIAS | F_SWIZ);
}